// round 8
// baseline (speedup 1.0000x reference)
#include <cuda_runtime.h>
#include <math.h>
#include <stdint.h>

#define OBS   128
#define PROJ  64
#define HID   256
#define LAT   24
#define BB    1024
#define TT    256
#define G3    768
#define KC4   28                         // k4-blocks cached in SMEM (k = 0..111)
#define WSM_BYTES (KC4 * 3 * 128 * 16)   // 168 KB weight cache

// ---- device scratch --------------------------------------------------------
__device__ float  g_gx [(size_t)BB * TT * G3];
__device__ float  g_seq[(size_t)BB * TT * HID];
__device__ float4 g_Wt4[(HID / 4) * G3];         // [k4][col], 4 k's packed

// ---- helpers ---------------------------------------------------------------
__device__ __forceinline__ void fma2(float2& d, float2 a, float2 b) {
    unsigned long long& dd = reinterpret_cast<unsigned long long&>(d);
    asm("fma.rn.f32x2 %0, %1, %2, %0;"
        : "+l"(dd)
        : "l"(reinterpret_cast<const unsigned long long&>(a)),
          "l"(reinterpret_cast<const unsigned long long&>(b)));
}
__device__ __forceinline__ float tanha(float x) {
    float y; asm("tanh.approx.f32 %0, %1;" : "=f"(y) : "f"(x)); return y;
}
__device__ __forceinline__ float siga(float x) {
    return fmaf(0.5f, tanha(0.5f * x), 0.5f);
}

// ---- W_hh repack ------------------------------------------------------------
__global__ void tr_kernel(const float* __restrict__ W) {
    int idx = blockIdx.x * 256 + threadIdx.x;
    if (idx >= (HID / 4) * G3) return;
    int k4 = idx / G3, col = idx - k4 * G3;
    float4 v;
    v.x = W[(size_t)(4 * k4 + 0) * G3 + col];
    v.y = W[(size_t)(4 * k4 + 1) * G3 + col];
    v.z = W[(size_t)(4 * k4 + 2) * G3 + col];
    v.w = W[(size_t)(4 * k4 + 3) * G3 + col];
    g_Wt4[idx] = v;
}

// ---- pre (unchanged, proven) -----------------------------------------------
__global__ __launch_bounds__(256) void pre_kernel(
    const float* __restrict__ obs, const float* __restrict__ W_in,
    const float* __restrict__ b_in, const float* __restrict__ W_ih,
    const float* __restrict__ b_ih)
{
    __shared__ float s_obsT[OBS][34];
    __shared__ float s_x2[PROJ][34];

    const int tid = threadIdx.x;
    const size_t row0 = (size_t)blockIdx.x * 32;

    for (int i = tid; i < 32 * OBS; i += 256) {
        int r = i >> 7, k = i & 127;
        s_obsT[k][r] = obs[(row0 + r) * OBS + k];
    }
    __syncthreads();

    {
        const int p = tid & 63, rh = tid >> 6;
        const float bi = b_in[p];
        float2 acc[4];
        #pragma unroll
        for (int pr = 0; pr < 4; pr++) acc[pr] = make_float2(bi, bi);
        #pragma unroll 4
        for (int k = 0; k < OBS; k++) {
            float w = W_in[k * PROJ + p];
            float2 w2 = make_float2(w, w);
            #pragma unroll
            for (int pr = 0; pr < 4; pr++)
                fma2(acc[pr], w2, *(const float2*)&s_obsT[k][8 * rh + 2 * pr]);
        }
        #pragma unroll
        for (int pr = 0; pr < 4; pr++) {
            s_x2[p][8 * rh + 2 * pr]     = acc[pr].x;
            s_x2[p][8 * rh + 2 * pr + 1] = acc[pr].y;
        }
    }
    __syncthreads();

    const int j = tid;
    const float bh0 = b_ih[j], bh1 = b_ih[j + 256], bh2 = b_ih[j + 512];
    for (int rt = 0; rt < 2; rt++) {
        float2 a0[8], a1[8], a2[8];
        #pragma unroll
        for (int pr = 0; pr < 8; pr++) {
            a0[pr] = make_float2(bh0, bh0);
            a1[pr] = make_float2(bh1, bh1);
            a2[pr] = make_float2(bh2, bh2);
        }
        #pragma unroll 2
        for (int p = 0; p < PROJ; p++) {
            float w0 = W_ih[p * G3 + j];
            float w1 = W_ih[p * G3 + j + 256];
            float w2 = W_ih[p * G3 + j + 512];
            float2 w02 = make_float2(w0, w0);
            float2 w12 = make_float2(w1, w1);
            float2 w22 = make_float2(w2, w2);
            #pragma unroll
            for (int pr = 0; pr < 8; pr++) {
                float2 xv = *(const float2*)&s_x2[p][16 * rt + 2 * pr];
                fma2(a0[pr], w02, xv);
                fma2(a1[pr], w12, xv);
                fma2(a2[pr], w22, xv);
            }
        }
        #pragma unroll
        for (int pr = 0; pr < 8; pr++) {
            size_t r = row0 + rt * 16 + 2 * pr;
            g_gx[r * G3 + j]             = a0[pr].x;
            g_gx[(r + 1) * G3 + j]       = a0[pr].y;
            g_gx[r * G3 + j + 256]       = a1[pr].x;
            g_gx[(r + 1) * G3 + j + 256] = a1[pr].y;
            g_gx[r * G3 + j + 512]       = a2[pr].x;
            g_gx[(r + 1) * G3 + j + 512] = a2[pr].y;
        }
    }
}

// ---- rec: cluster-2 scan, f32x2 paired along K ------------------------------
// 64 clusters x 2 CTAs, 256 threads. CTA rank q: units q*128..+127.
// Thread: uu = tid&127, rg = tid>>7 -> rows 8rg..8rg+7.
// h row-major in SMEM: s_h[buf][row][k]. Both FFMA2 operands are natural
// aligned pairs (w from float4, h from broadcast LDS.128) -> no dup MOVs.

// one k4 of gate FMAs for all 8 rows
#define K4_FMA(wr, wz, wn, k4i)                                               \
    {                                                                         \
        float2 wr01 = make_float2(wr.x, wr.y), wr23 = make_float2(wr.z, wr.w);\
        float2 wz01 = make_float2(wz.x, wz.y), wz23 = make_float2(wz.z, wz.w);\
        float2 wn01 = make_float2(wn.x, wn.y), wn23 = make_float2(wn.z, wn.w);\
        _Pragma("unroll")                                                     \
        for (int r = 0; r < 8; r++) {                                         \
            float4 hv = *(const float4*)&s_h[rb][r0 + r][4 * (k4i)];          \
            float2 h01 = make_float2(hv.x, hv.y);                             \
            float2 h23 = make_float2(hv.z, hv.w);                             \
            fma2(aR[r], wr01, h01); fma2(aZ[r], wz01, h01);                   \
            fma2(aN[r], wn01, h01);                                           \
            fma2(aR[r], wr23, h23); fma2(aZ[r], wz23, h23);                   \
            fma2(aN[r], wn23, h23);                                           \
        }                                                                     \
    }

// load 2 k4-blocks of streamed weights into a 6-float4 buffer
#define LDW2(dst, k4b)                                          \
    {                                                           \
        _Pragma("unroll")                                       \
        for (int u = 0; u < 2; u++) {                           \
            size_t kb = (size_t)((k4b) + u) * G3;               \
            dst[3 * u + 0] = g_Wt4[kb + gu];                    \
            dst[3 * u + 1] = g_Wt4[kb + 256 + gu];              \
            dst[3 * u + 2] = g_Wt4[kb + 512 + gu];              \
        }                                                       \
    }

#define COMP2(buf, k4b)                                         \
    {                                                           \
        K4_FMA(buf[0], buf[1], buf[2], (k4b));                  \
        K4_FMA(buf[3], buf[4], buf[5], (k4b) + 1);              \
    }

__global__ __launch_bounds__(256, 1) __cluster_dims__(2, 1, 1)
void rec_kernel(const int* __restrict__ is_init, const float* __restrict__ hx,
                const float* __restrict__ b_hh, float* __restrict__ h_final)
{
    __shared__ float s_h[2][16][HID];           // 32 KB, row-major
    __shared__ unsigned char s_rst[16][TT];     //  4 KB
    extern __shared__ float4 s_wc[];            // 168 KB weight cache

    const int tid = threadIdx.x;
    const int q   = blockIdx.x & 1;
    const int b0  = (blockIdx.x >> 1) * 16;
    const int uu  = tid & 127;
    const int rg  = tid >> 7;
    const int gu  = q * 128 + uu;
    const int r0  = rg * 8;

    // fill weight cache (k4 = 0..KC4-1)
    for (int i = tid; i < KC4 * 3 * 128; i += 256) {
        int k4 = i / 384, rem = i - k4 * 384;
        int g = rem >> 7, u2 = rem & 127;
        s_wc[i] = g_Wt4[(size_t)k4 * G3 + g * 256 + q * 128 + u2];
    }
    for (int i = tid; i < 16 * TT; i += 256) {
        int r = i >> 8, t = i & 255;
        s_rst[r][t] = (unsigned char)(is_init[(b0 + r) * TT + t] != 0);
    }
    // init h buffer 0 (t=0 masked hx), row-major
    for (int i = tid; i < 16 * HID; i += 256) {
        int r = i >> 8, k = i & 255;
        float h = (is_init[(b0 + r) * TT] != 0) ? 0.f : hx[(size_t)(b0 + r) * HID + k];
        s_h[0][r][k] = h;
    }
    __syncthreads();

    const float bhr = b_hh[gu], bhz = b_hh[256 + gu], bhn = b_hh[512 + gu];

    uint32_t my_base;
    asm("{ .reg .u64 t0; cvta.to.shared.u64 t0, %1; cvt.u32.u64 %0, t0; }"
        : "=r"(my_base) : "l"(&s_h[0][0][0]));
    uint32_t peer_base;
    asm("mapa.shared::cluster.u32 %0, %1, %2;"
        : "=r"(peer_base) : "r"(my_base), "r"(q ^ 1));

    for (int t = 0; t < TT; t++) {
        const int rb = t & 1, wb = rb ^ 1;

        // prefetch input-side gates
        float gxr[8], gxz[8], gxn[8];
        #pragma unroll
        for (int r = 0; r < 8; r++) {
            const float* g = g_gx + ((size_t)(b0 + r0 + r) * TT + t) * G3;
            gxr[r] = g[gu]; gxz[r] = g[256 + gu]; gxn[r] = g[512 + gu];
        }

        float2 aR[8], aZ[8], aN[8];
        #pragma unroll
        for (int r = 0; r < 8; r++) {
            aR[r] = make_float2(0.f, 0.f);
            aZ[r] = make_float2(0.f, 0.f);
            aN[r] = make_float2(0.f, 0.f);
        }

        // prime streamed weights (hide L2 latency behind cached part)
        float4 wA[6], wB[6];
        LDW2(wA, KC4);
        LDW2(wB, KC4 + 2);

        // part 1: k4 = 0..27 from SMEM cache
        #pragma unroll 4
        for (int k4 = 0; k4 < KC4; k4++) {
            float4 wr = s_wc[(k4 * 3 + 0) * 128 + uu];
            float4 wz = s_wc[(k4 * 3 + 1) * 128 + uu];
            float4 wn = s_wc[(k4 * 3 + 2) * 128 + uu];
            K4_FMA(wr, wz, wn, k4);
        }

        // part 2: k4 = 28..63 streamed, double-buffered (2-k4 blocks)
        #pragma unroll 1
        for (int k4b = KC4; k4b < 60; k4b += 4) {
            COMP2(wA, k4b);
            LDW2(wA, k4b + 4);
            COMP2(wB, k4b + 2);
            LDW2(wB, k4b + 6);
        }
        COMP2(wA, 60);
        COMP2(wB, 62);

        // gates: horizontal combine + MUFU.TANH
        float hnew[8];
        #pragma unroll
        for (int r = 0; r < 8; r++) {
            float hp = s_h[rb][r0 + r][gu];
            float rr = siga(gxr[r] + aR[r].x + aR[r].y + bhr);
            float zz = siga(gxz[r] + aZ[r].x + aZ[r].y + bhz);
            float nn = tanha(gxn[r] + rr * (aN[r].x + aN[r].y + bhn));
            hnew[r] = nn + zz * (hp - nn);
        }

        if (t == TT - 1) {
            #pragma unroll
            for (int r = 0; r < 8; r++) {
                g_seq[((size_t)(b0 + r0 + r) * TT + t) * HID + gu] = hnew[r];
                h_final[(size_t)(b0 + r0 + r) * HID + gu] = hnew[r];
            }
            break;
        }

        // write (t+1)-masked h: local + peer; overlap g_seq stores w/ barrier
        #pragma unroll
        for (int r = 0; r < 8; r++) {
            float v = s_rst[r0 + r][t + 1] ? 0.f : hnew[r];
            s_h[wb][r0 + r][gu] = v;
            uint32_t off = (uint32_t)(((wb * 16 + r0 + r) * HID + gu) * sizeof(float));
            asm volatile("st.shared::cluster.b32 [%0], %1;"
                         :: "r"(peer_base + off), "f"(v) : "memory");
        }
        asm volatile("barrier.cluster.arrive.aligned;" ::: "memory");
        #pragma unroll
        for (int r = 0; r < 8; r++)
            g_seq[((size_t)(b0 + r0 + r) * TT + t) * HID + gu] = hnew[r];
        asm volatile("barrier.cluster.wait.aligned;" ::: "memory");
    }
}

// ---- post (unchanged) -------------------------------------------------------
__global__ __launch_bounds__(256) void post_kernel(
    const float* __restrict__ W_out, const float* __restrict__ b_out,
    float* __restrict__ out)
{
    __shared__ float s_m2[HID][32];

    const int tid = threadIdx.x;
    const size_t row0 = (size_t)blockIdx.x * 32;

    {
        const int row = tid & 31;
        const int kc  = (tid >> 5) * 32;
        const float* src = g_seq + (row0 + row) * HID + kc;
        #pragma unroll
        for (int c = 0; c < 8; c++) {
            float4 v = *(const float4*)(src + 4 * c);
            float hv[4] = {v.x, v.y, v.z, v.w};
            #pragma unroll
            for (int e = 0; e < 4; e++) {
                float h = hv[e];
                float sp = __logf(1.f + __expf(h));
                s_m2[kc + 4 * c + e][row] = h * tanha(sp);
            }
        }
    }
    __syncthreads();

    if (tid < 192) {
        const int pg = tid / 24;
        const int l  = tid - pg * 24;
        float2 a0 = make_float2(0.f, 0.f), a1 = make_float2(0.f, 0.f);
        #pragma unroll 4
        for (int k = 0; k < HID; k++) {
            float4 m4 = *(const float4*)&s_m2[k][4 * pg];
            float w = __ldg(W_out + k * LAT + l);
            float2 w2 = make_float2(w, w);
            fma2(a0, w2, make_float2(m4.x, m4.y));
            fma2(a1, w2, make_float2(m4.z, m4.w));
        }
        const float bl = b_out[l];
        out[(row0 + 4 * pg + 0) * LAT + l] = a0.x + bl;
        out[(row0 + 4 * pg + 1) * LAT + l] = a0.y + bl;
        out[(row0 + 4 * pg + 2) * LAT + l] = a1.x + bl;
        out[(row0 + 4 * pg + 3) * LAT + l] = a1.y + bl;
    }
}

// ---------------------------------------------------------------------------
extern "C" void kernel_launch(void* const* d_in, const int* in_sizes, int n_in,
                              void* d_out, int out_size) {
    const float* obs     = (const float*)d_in[0];
    const int*   is_init = (const int*)  d_in[1];
    const float* hx      = (const float*)d_in[2];
    const float* W_in    = (const float*)d_in[3];
    const float* b_in    = (const float*)d_in[4];
    const float* W_ih    = (const float*)d_in[5];
    const float* b_ih    = (const float*)d_in[6];
    const float* W_hh    = (const float*)d_in[7];
    const float* b_hh    = (const float*)d_in[8];
    const float* W_out   = (const float*)d_in[9];
    const float* b_out   = (const float*)d_in[10];

    float* out     = (float*)d_out;                 // [B,T,LAT]
    float* h_final = out + (size_t)BB * TT * LAT;   // [B,HID]

    cudaFuncSetAttribute(rec_kernel,
                         cudaFuncAttributeMaxDynamicSharedMemorySize, WSM_BYTES);

    tr_kernel<<<((HID / 4) * G3 + 255) / 256, 256>>>(W_hh);
    pre_kernel<<<(BB * TT) / 32, 256>>>(obs, W_in, b_in, W_ih, b_ih);
    rec_kernel<<<BB / 8, 256, WSM_BYTES>>>(is_init, hx, b_hh, h_final);
    post_kernel<<<(BB * TT) / 32, 256>>>(W_out, b_out, out);
}

// round 9
// speedup vs baseline: 1.1182x; 1.1182x over previous
#include <cuda_runtime.h>
#include <math.h>
#include <stdint.h>

#define OBS   128
#define PROJ  64
#define HID   256
#define LAT   24
#define BB    1024
#define TT    256
#define G3    768
#define KC4   28                         // k4-blocks cached in SMEM (k = 0..111)
#define WSM_BYTES (KC4 * 3 * 128 * 16)   // 168 KB weight cache
#define NCLU  74
#define RPC   14                         // rows per cluster
#define RPT   7                          // rows per thread-half

// ---- device scratch --------------------------------------------------------
__device__ float  g_gx [(size_t)BB * TT * G3];
__device__ float  g_seq[(size_t)BB * TT * HID];
__device__ float4 g_Wt4[(HID / 4) * G3];         // [k4][col], 4 k's packed

// ---- helpers ---------------------------------------------------------------
__device__ __forceinline__ void fma2(float2& d, float2 a, float2 b) {
    unsigned long long& dd = reinterpret_cast<unsigned long long&>(d);
    asm("fma.rn.f32x2 %0, %1, %2, %0;"
        : "+l"(dd)
        : "l"(reinterpret_cast<const unsigned long long&>(a)),
          "l"(reinterpret_cast<const unsigned long long&>(b)));
}
__device__ __forceinline__ float tanha(float x) {
    float y; asm("tanh.approx.f32 %0, %1;" : "=f"(y) : "f"(x)); return y;
}
__device__ __forceinline__ float siga(float x) {
    return fmaf(0.5f, tanha(0.5f * x), 0.5f);
}

// ---- W_hh repack ------------------------------------------------------------
__global__ void tr_kernel(const float* __restrict__ W) {
    int idx = blockIdx.x * 256 + threadIdx.x;
    if (idx >= (HID / 4) * G3) return;
    int k4 = idx / G3, col = idx - k4 * G3;
    float4 v;
    v.x = W[(size_t)(4 * k4 + 0) * G3 + col];
    v.y = W[(size_t)(4 * k4 + 1) * G3 + col];
    v.z = W[(size_t)(4 * k4 + 2) * G3 + col];
    v.w = W[(size_t)(4 * k4 + 3) * G3 + col];
    g_Wt4[idx] = v;
}

// ---- pre (unchanged, proven) -----------------------------------------------
__global__ __launch_bounds__(256) void pre_kernel(
    const float* __restrict__ obs, const float* __restrict__ W_in,
    const float* __restrict__ b_in, const float* __restrict__ W_ih,
    const float* __restrict__ b_ih)
{
    __shared__ float s_obsT[OBS][34];
    __shared__ float s_x2[PROJ][34];

    const int tid = threadIdx.x;
    const size_t row0 = (size_t)blockIdx.x * 32;

    for (int i = tid; i < 32 * OBS; i += 256) {
        int r = i >> 7, k = i & 127;
        s_obsT[k][r] = obs[(row0 + r) * OBS + k];
    }
    __syncthreads();

    {
        const int p = tid & 63, rh = tid >> 6;
        const float bi = b_in[p];
        float2 acc[4];
        #pragma unroll
        for (int pr = 0; pr < 4; pr++) acc[pr] = make_float2(bi, bi);
        #pragma unroll 4
        for (int k = 0; k < OBS; k++) {
            float w = W_in[k * PROJ + p];
            float2 w2 = make_float2(w, w);
            #pragma unroll
            for (int pr = 0; pr < 4; pr++)
                fma2(acc[pr], w2, *(const float2*)&s_obsT[k][8 * rh + 2 * pr]);
        }
        #pragma unroll
        for (int pr = 0; pr < 4; pr++) {
            s_x2[p][8 * rh + 2 * pr]     = acc[pr].x;
            s_x2[p][8 * rh + 2 * pr + 1] = acc[pr].y;
        }
    }
    __syncthreads();

    const int j = tid;
    const float bh0 = b_ih[j], bh1 = b_ih[j + 256], bh2 = b_ih[j + 512];
    for (int rt = 0; rt < 2; rt++) {
        float2 a0[8], a1[8], a2[8];
        #pragma unroll
        for (int pr = 0; pr < 8; pr++) {
            a0[pr] = make_float2(bh0, bh0);
            a1[pr] = make_float2(bh1, bh1);
            a2[pr] = make_float2(bh2, bh2);
        }
        #pragma unroll 2
        for (int p = 0; p < PROJ; p++) {
            float w0 = W_ih[p * G3 + j];
            float w1 = W_ih[p * G3 + j + 256];
            float w2 = W_ih[p * G3 + j + 512];
            float2 w02 = make_float2(w0, w0);
            float2 w12 = make_float2(w1, w1);
            float2 w22 = make_float2(w2, w2);
            #pragma unroll
            for (int pr = 0; pr < 8; pr++) {
                float2 xv = *(const float2*)&s_x2[p][16 * rt + 2 * pr];
                fma2(a0[pr], w02, xv);
                fma2(a1[pr], w12, xv);
                fma2(a2[pr], w22, xv);
            }
        }
        #pragma unroll
        for (int pr = 0; pr < 8; pr++) {
            size_t r = row0 + rt * 16 + 2 * pr;
            g_gx[r * G3 + j]             = a0[pr].x;
            g_gx[(r + 1) * G3 + j]       = a0[pr].y;
            g_gx[r * G3 + j + 256]       = a1[pr].x;
            g_gx[(r + 1) * G3 + j + 256] = a1[pr].y;
            g_gx[r * G3 + j + 512]       = a2[pr].x;
            g_gx[(r + 1) * G3 + j + 512] = a2[pr].y;
        }
    }
}

// ---- rec: 74 clusters x 2 CTAs (all 148 SMs), 14 rows/cluster ---------------
// CTA rank q: units q*128..+127. Thread: uu = tid&127, rg = tid>>7 ->
// rows rg*7..rg*7+6. k-paired f32x2; h row-major s_h[buf][row][k].
// Rows >= BB are padding (zeros, stores guarded).

#define K4_FMA(wr, wz, wn, k4i)                                               \
    {                                                                         \
        float2 wr01 = make_float2(wr.x, wr.y), wr23 = make_float2(wr.z, wr.w);\
        float2 wz01 = make_float2(wz.x, wz.y), wz23 = make_float2(wz.z, wz.w);\
        float2 wn01 = make_float2(wn.x, wn.y), wn23 = make_float2(wn.z, wn.w);\
        _Pragma("unroll")                                                     \
        for (int r = 0; r < RPT; r++) {                                       \
            float4 hv = *(const float4*)&s_h[rb][r0 + r][4 * (k4i)];          \
            float2 h01 = make_float2(hv.x, hv.y);                             \
            float2 h23 = make_float2(hv.z, hv.w);                             \
            fma2(aR[r], wr01, h01); fma2(aZ[r], wz01, h01);                   \
            fma2(aN[r], wn01, h01);                                           \
            fma2(aR[r], wr23, h23); fma2(aZ[r], wz23, h23);                   \
            fma2(aN[r], wn23, h23);                                           \
        }                                                                     \
    }

#define LDW2(dst, k4b)                                          \
    {                                                           \
        _Pragma("unroll")                                       \
        for (int u = 0; u < 2; u++) {                           \
            size_t kb = (size_t)((k4b) + u) * G3;               \
            dst[3 * u + 0] = g_Wt4[kb + gu];                    \
            dst[3 * u + 1] = g_Wt4[kb + 256 + gu];              \
            dst[3 * u + 2] = g_Wt4[kb + 512 + gu];              \
        }                                                       \
    }

#define COMP2(buf, k4b)                                         \
    {                                                           \
        K4_FMA(buf[0], buf[1], buf[2], (k4b));                  \
        K4_FMA(buf[3], buf[4], buf[5], (k4b) + 1);              \
    }

__global__ __launch_bounds__(256, 1) __cluster_dims__(2, 1, 1)
void rec_kernel(const int* __restrict__ is_init, const float* __restrict__ hx,
                const float* __restrict__ b_hh, float* __restrict__ h_final)
{
    __shared__ float s_h[2][RPC][HID];          // 28 KB
    __shared__ unsigned char s_rst[RPC][TT];    // 3.5 KB
    extern __shared__ float4 s_wc[];            // 168 KB weight cache

    const int tid = threadIdx.x;
    const int q   = blockIdx.x & 1;
    const int b0  = (blockIdx.x >> 1) * RPC;
    const int uu  = tid & 127;
    const int rg  = tid >> 7;
    const int gu  = q * 128 + uu;
    const int r0  = rg * RPT;

    // fill weight cache (k4 = 0..KC4-1)
    for (int i = tid; i < KC4 * 3 * 128; i += 256) {
        int k4 = i / 384, rem = i - k4 * 384;
        int g = rem >> 7, u2 = rem & 127;
        s_wc[i] = g_Wt4[(size_t)k4 * G3 + g * 256 + q * 128 + u2];
    }
    // reset masks (padding rows -> always reset, harmless)
    for (int i = tid; i < RPC * TT; i += 256) {
        int r = i >> 8, t = i & 255;
        int row = b0 + r;
        s_rst[r][t] = (row < BB) ? (unsigned char)(is_init[row * TT + t] != 0) : 1;
    }
    // init h buffer 0 (t=0 masked hx); padding rows -> 0
    for (int i = tid; i < RPC * HID; i += 256) {
        int r = i >> 8, k = i & 255;
        int row = b0 + r;
        float h = 0.f;
        if (row < BB && is_init[row * TT] == 0) h = hx[(size_t)row * HID + k];
        s_h[0][r][k] = h;
    }
    __syncthreads();

    const float bhr = b_hh[gu], bhz = b_hh[256 + gu], bhn = b_hh[512 + gu];

    uint32_t my_base;
    asm("{ .reg .u64 t0; cvta.to.shared.u64 t0, %1; cvt.u32.u64 %0, t0; }"
        : "=r"(my_base) : "l"(&s_h[0][0][0]));
    uint32_t peer_base;
    asm("mapa.shared::cluster.u32 %0, %1, %2;"
        : "=r"(peer_base) : "r"(my_base), "r"(q ^ 1));

    // clamped row indices for gx loads (values of clamped rows never stored)
    int rowc[RPT];
    bool rowv[RPT];
    #pragma unroll
    for (int r = 0; r < RPT; r++) {
        int row = b0 + r0 + r;
        rowv[r] = (row < BB);
        rowc[r] = rowv[r] ? row : (BB - 1);
    }

    for (int t = 0; t < TT; t++) {
        const int rb = t & 1, wb = rb ^ 1;

        // prefetch input-side gates
        float gxr[RPT], gxz[RPT], gxn[RPT];
        #pragma unroll
        for (int r = 0; r < RPT; r++) {
            const float* g = g_gx + ((size_t)rowc[r] * TT + t) * G3;
            gxr[r] = g[gu]; gxz[r] = g[256 + gu]; gxn[r] = g[512 + gu];
        }

        float2 aR[RPT], aZ[RPT], aN[RPT];
        #pragma unroll
        for (int r = 0; r < RPT; r++) {
            aR[r] = make_float2(0.f, 0.f);
            aZ[r] = make_float2(0.f, 0.f);
            aN[r] = make_float2(0.f, 0.f);
        }

        // prime streamed weights
        float4 wA[6], wB[6];
        LDW2(wA, KC4);
        LDW2(wB, KC4 + 2);

        // part 1: k4 = 0..27 from SMEM cache
        #pragma unroll 4
        for (int k4 = 0; k4 < KC4; k4++) {
            float4 wr = s_wc[(k4 * 3 + 0) * 128 + uu];
            float4 wz = s_wc[(k4 * 3 + 1) * 128 + uu];
            float4 wn = s_wc[(k4 * 3 + 2) * 128 + uu];
            K4_FMA(wr, wz, wn, k4);
        }

        // part 2: k4 = 28..63 streamed, double-buffered
        #pragma unroll 1
        for (int k4b = KC4; k4b < 60; k4b += 4) {
            COMP2(wA, k4b);
            LDW2(wA, k4b + 4);
            COMP2(wB, k4b + 2);
            LDW2(wB, k4b + 6);
        }
        COMP2(wA, 60);
        COMP2(wB, 62);

        // gates
        float hnew[RPT];
        #pragma unroll
        for (int r = 0; r < RPT; r++) {
            float hp = s_h[rb][r0 + r][gu];
            float rr = siga(gxr[r] + aR[r].x + aR[r].y + bhr);
            float zz = siga(gxz[r] + aZ[r].x + aZ[r].y + bhz);
            float nn = tanha(gxn[r] + rr * (aN[r].x + aN[r].y + bhn));
            hnew[r] = nn + zz * (hp - nn);
        }

        if (t == TT - 1) {
            #pragma unroll
            for (int r = 0; r < RPT; r++) {
                if (rowv[r]) {
                    g_seq[((size_t)rowc[r] * TT + t) * HID + gu] = hnew[r];
                    h_final[(size_t)rowc[r] * HID + gu] = hnew[r];
                }
            }
            break;
        }

        // write (t+1)-masked h: local + peer; overlap g_seq stores w/ barrier
        #pragma unroll
        for (int r = 0; r < RPT; r++) {
            float v = s_rst[r0 + r][t + 1] ? 0.f : hnew[r];
            s_h[wb][r0 + r][gu] = v;
            uint32_t off = (uint32_t)(((wb * RPC + r0 + r) * HID + gu) * sizeof(float));
            asm volatile("st.shared::cluster.b32 [%0], %1;"
                         :: "r"(peer_base + off), "f"(v) : "memory");
        }
        asm volatile("barrier.cluster.arrive.aligned;" ::: "memory");
        #pragma unroll
        for (int r = 0; r < RPT; r++)
            if (rowv[r])
                g_seq[((size_t)rowc[r] * TT + t) * HID + gu] = hnew[r];
        asm volatile("barrier.cluster.wait.aligned;" ::: "memory");
    }
}

// ---- post: out = mish(seq) @ W_out + b_out, W_out in SMEM ------------------
__global__ __launch_bounds__(256) void post_kernel(
    const float* __restrict__ W_out, const float* __restrict__ b_out,
    float* __restrict__ out)
{
    __shared__ float s_m2[HID][32];     // 32 KB
    __shared__ float s_w[HID * LAT];    // 24 KB

    const int tid = threadIdx.x;
    const size_t row0 = (size_t)blockIdx.x * 32;

    for (int i = tid; i < HID * LAT; i += 256) s_w[i] = W_out[i];
    {
        const int row = tid & 31;
        const int kc  = (tid >> 5) * 32;
        const float* src = g_seq + (row0 + row) * HID + kc;
        #pragma unroll
        for (int c = 0; c < 8; c++) {
            float4 v = *(const float4*)(src + 4 * c);
            float hv[4] = {v.x, v.y, v.z, v.w};
            #pragma unroll
            for (int e = 0; e < 4; e++) {
                float h = hv[e];
                float sp = __logf(1.f + __expf(h));
                s_m2[kc + 4 * c + e][row] = h * tanha(sp);
            }
        }
    }
    __syncthreads();

    if (tid < 192) {
        const int pg = tid / 24;
        const int l  = tid - pg * 24;
        float2 a0 = make_float2(0.f, 0.f), a1 = make_float2(0.f, 0.f);
        #pragma unroll 4
        for (int k = 0; k < HID; k++) {
            float4 m4 = *(const float4*)&s_m2[k][4 * pg];
            float w = s_w[k * LAT + l];
            float2 w2 = make_float2(w, w);
            fma2(a0, w2, make_float2(m4.x, m4.y));
            fma2(a1, w2, make_float2(m4.z, m4.w));
        }
        const float bl = b_out[l];
        out[(row0 + 4 * pg + 0) * LAT + l] = a0.x + bl;
        out[(row0 + 4 * pg + 1) * LAT + l] = a0.y + bl;
        out[(row0 + 4 * pg + 2) * LAT + l] = a1.x + bl;
        out[(row0 + 4 * pg + 3) * LAT + l] = a1.y + bl;
    }
}

// ---------------------------------------------------------------------------
extern "C" void kernel_launch(void* const* d_in, const int* in_sizes, int n_in,
                              void* d_out, int out_size) {
    const float* obs     = (const float*)d_in[0];
    const int*   is_init = (const int*)  d_in[1];
    const float* hx      = (const float*)d_in[2];
    const float* W_in    = (const float*)d_in[3];
    const float* b_in    = (const float*)d_in[4];
    const float* W_ih    = (const float*)d_in[5];
    const float* b_ih    = (const float*)d_in[6];
    const float* W_hh    = (const float*)d_in[7];
    const float* b_hh    = (const float*)d_in[8];
    const float* W_out   = (const float*)d_in[9];
    const float* b_out   = (const float*)d_in[10];

    float* out     = (float*)d_out;                 // [B,T,LAT]
    float* h_final = out + (size_t)BB * TT * LAT;   // [B,HID]

    cudaFuncSetAttribute(rec_kernel,
                         cudaFuncAttributeMaxDynamicSharedMemorySize, WSM_BYTES);

    tr_kernel<<<((HID / 4) * G3 + 255) / 256, 256>>>(W_hh);
    pre_kernel<<<(BB * TT) / 32, 256>>>(obs, W_in, b_in, W_ih, b_ih);
    rec_kernel<<<NCLU * 2, 256, WSM_BYTES>>>(is_init, hx, b_hh, h_final);
    post_kernel<<<(BB * TT) / 32, 256>>>(W_out, b_out, out);
}

// round 10
// speedup vs baseline: 1.6729x; 1.4961x over previous
#include <cuda_runtime.h>
#include <math.h>
#include <stdint.h>

#define OBS   128
#define PROJ  64
#define HID   256
#define LAT   24
#define BB    1024
#define TT    256
#define G3    768

#define KCC   13                      // k-chunks cached in SMEM (of 32)
#define HSTR  260                     // s_h row stride (conflict-free a-frags)
#define GSTR  388                     // s_gh row stride

// ---- device scratch --------------------------------------------------------
__device__ float    g_gx [(size_t)BB * TT * G3];
__device__ float    g_seq[(size_t)BB * TT * HID];
// W_hh repacked to mma b-fragment stream order, tf32:
// [q][kc][warp][lane][j0b0,j0b1,j1b0,j1b1, j2b0,...,j5b1]  (12 u32 per lane)
__device__ uint4    g_Wm[2 * 32 * 8 * 32 * 3];

// ---- helpers ---------------------------------------------------------------
__device__ __forceinline__ void fma2(float2& d, float2 a, float2 b) {
    unsigned long long& dd = reinterpret_cast<unsigned long long&>(d);
    asm("fma.rn.f32x2 %0, %1, %2, %0;"
        : "+l"(dd)
        : "l"(reinterpret_cast<const unsigned long long&>(a)),
          "l"(reinterpret_cast<const unsigned long long&>(b)));
}
__device__ __forceinline__ float tanha(float x) {
    float y; asm("tanh.approx.f32 %0, %1;" : "=f"(y) : "f"(x)); return y;
}
__device__ __forceinline__ float siga(float x) {
    return fmaf(0.5f, tanha(0.5f * x), 0.5f);
}
__device__ __forceinline__ uint32_t to_tf32(float f) {
    uint32_t r; asm("cvt.rna.tf32.f32 %0, %1;" : "=r"(r) : "f"(f)); return r;
}

#define MMA(cp, a0, a1, a2, a3, b0, b1)                                 \
    asm("mma.sync.aligned.m16n8k8.row.col.f32.tf32.tf32.f32 "           \
        "{%0,%1,%2,%3}, {%4,%5,%6,%7}, {%8,%9}, {%0,%1,%2,%3};"         \
        : "+f"((cp)[0]), "+f"((cp)[1]), "+f"((cp)[2]), "+f"((cp)[3])    \
        : "r"(a0), "r"(a1), "r"(a2), "r"(a3), "r"(b0), "r"(b1))

// ---- trm: repack W_hh into mma b-frag stream order (tf32) ------------------
// n_local in [0,384): 0..127 -> r-gate, 128..255 -> z, 256..383 -> n
// for CTA half q.  b0 = W[kc*8+tk][gcol], b1 = W[kc*8+tk+4][gcol].
__global__ void trm_kernel(const float* __restrict__ W) {
    int idx = blockIdx.x * 256 + threadIdx.x;   // 2*32*8*32*6 = 98304
    if (idx >= 98304) return;
    int j = idx % 6;  int t = idx / 6;
    int lane = t & 31; t >>= 5;
    int w = t & 7;     t >>= 3;
    int kc = t & 31;   t >>= 5;
    int q = t;
    int tk = lane & 3, g = lane >> 2;
    int n_local = w * 48 + j * 8 + g;
    int gate = n_local >> 7, u = n_local & 127;
    int gcol = gate * 256 + q * 128 + u;
    uint32_t* dst = (uint32_t*)g_Wm;
    size_t base = ((((size_t)q * 32 + kc) * 8 + w) * 32 + lane) * 12 + j * 2;
    dst[base]     = to_tf32(W[(size_t)(kc * 8 + tk)     * G3 + gcol]);
    dst[base + 1] = to_tf32(W[(size_t)(kc * 8 + tk + 4) * G3 + gcol]);
}

// ---- pre (unchanged, proven) -----------------------------------------------
__global__ __launch_bounds__(256) void pre_kernel(
    const float* __restrict__ obs, const float* __restrict__ W_in,
    const float* __restrict__ b_in, const float* __restrict__ W_ih,
    const float* __restrict__ b_ih)
{
    __shared__ float s_obsT[OBS][34];
    __shared__ float s_x2[PROJ][34];

    const int tid = threadIdx.x;
    const size_t row0 = (size_t)blockIdx.x * 32;

    for (int i = tid; i < 32 * OBS; i += 256) {
        int r = i >> 7, k = i & 127;
        s_obsT[k][r] = obs[(row0 + r) * OBS + k];
    }
    __syncthreads();

    {
        const int p = tid & 63, rh = tid >> 6;
        const float bi = b_in[p];
        float2 acc[4];
        #pragma unroll
        for (int pr = 0; pr < 4; pr++) acc[pr] = make_float2(bi, bi);
        #pragma unroll 4
        for (int k = 0; k < OBS; k++) {
            float w = W_in[k * PROJ + p];
            float2 w2 = make_float2(w, w);
            #pragma unroll
            for (int pr = 0; pr < 4; pr++)
                fma2(acc[pr], w2, *(const float2*)&s_obsT[k][8 * rh + 2 * pr]);
        }
        #pragma unroll
        for (int pr = 0; pr < 4; pr++) {
            s_x2[p][8 * rh + 2 * pr]     = acc[pr].x;
            s_x2[p][8 * rh + 2 * pr + 1] = acc[pr].y;
        }
    }
    __syncthreads();

    const int j = tid;
    const float bh0 = b_ih[j], bh1 = b_ih[j + 256], bh2 = b_ih[j + 512];
    for (int rt = 0; rt < 2; rt++) {
        float2 a0[8], a1[8], a2[8];
        #pragma unroll
        for (int pr = 0; pr < 8; pr++) {
            a0[pr] = make_float2(bh0, bh0);
            a1[pr] = make_float2(bh1, bh1);
            a2[pr] = make_float2(bh2, bh2);
        }
        #pragma unroll 2
        for (int p = 0; p < PROJ; p++) {
            float w0 = W_ih[p * G3 + j];
            float w1 = W_ih[p * G3 + j + 256];
            float w2 = W_ih[p * G3 + j + 512];
            float2 w02 = make_float2(w0, w0);
            float2 w12 = make_float2(w1, w1);
            float2 w22 = make_float2(w2, w2);
            #pragma unroll
            for (int pr = 0; pr < 8; pr++) {
                float2 xv = *(const float2*)&s_x2[p][16 * rt + 2 * pr];
                fma2(a0[pr], w02, xv);
                fma2(a1[pr], w12, xv);
                fma2(a2[pr], w22, xv);
            }
        }
        #pragma unroll
        for (int pr = 0; pr < 8; pr++) {
            size_t r = row0 + rt * 16 + 2 * pr;
            g_gx[r * G3 + j]             = a0[pr].x;
            g_gx[(r + 1) * G3 + j]       = a0[pr].y;
            g_gx[r * G3 + j + 256]       = a1[pr].x;
            g_gx[(r + 1) * G3 + j + 256] = a1[pr].y;
            g_gx[r * G3 + j + 512]       = a2[pr].x;
            g_gx[(r + 1) * G3 + j + 512] = a2[pr].y;
        }
    }
}

// ---- rec: cluster-2 scan, tf32 mma recurrent GEMM --------------------------
// 64 clusters x 2 CTAs x 256 thr. Cluster c: rows 16c..16c+15.
// CTA q: units q*128..+127 (384 gh cols: [r|z|n] x 128).
// mma: 8 warps x 6 n-tiles x 32 k-chunks, m16n8k8 tf32.
// k-chunks 0..12 from SMEM cache, 13..31 streamed from L2 (prepacked order).

#define SW_U4   (KCC * 8 * 32 * 3)               // 9984 uint4 = 156 KB
#define OFF_H   (SW_U4 * 16)                     // 159744
#define OFF_GH  (OFF_H + 2 * 16 * HSTR * 4)      // +33280 = 193024
#define OFF_RST (OFF_GH + 16 * GSTR * 4)         // +24832 = 217856
#define REC_SMEM (OFF_RST + 16 * TT)             // +4096  = 221952

#define LDGB(dst, kc_)                                                       \
    {                                                                        \
        const uint4* p = (const uint4*)g_Wm +                                \
            ((((size_t)q * 32 + (kc_)) * 8 + w) * 32 + lane) * 3;            \
        dst[0] = p[0]; dst[1] = p[1]; dst[2] = p[2];                         \
    }

#define COMPUTE_KC(bu, kc_)                                                  \
    {                                                                        \
        uint32_t a0 = to_tf32(s_h[hb + g       * HSTR + (kc_) * 8 + tk]);    \
        uint32_t a1 = to_tf32(s_h[hb + (g + 8) * HSTR + (kc_) * 8 + tk]);    \
        uint32_t a2 = to_tf32(s_h[hb + g       * HSTR + (kc_) * 8 + tk + 4]);\
        uint32_t a3 = to_tf32(s_h[hb + (g + 8) * HSTR + (kc_) * 8 + tk + 4]);\
        MMA(cc + 0,  a0, a1, a2, a3, bu[0].x, bu[0].y);                      \
        MMA(cc + 4,  a0, a1, a2, a3, bu[0].z, bu[0].w);                      \
        MMA(cc + 8,  a0, a1, a2, a3, bu[1].x, bu[1].y);                      \
        MMA(cc + 12, a0, a1, a2, a3, bu[1].z, bu[1].w);                      \
        MMA(cc + 16, a0, a1, a2, a3, bu[2].x, bu[2].y);                      \
        MMA(cc + 20, a0, a1, a2, a3, bu[2].z, bu[2].w);                      \
    }

__global__ __launch_bounds__(256, 1) __cluster_dims__(2, 1, 1)
void rec_kernel(const int* __restrict__ is_init, const float* __restrict__ hx,
                const float* __restrict__ b_hh, float* __restrict__ h_final)
{
    extern __shared__ char sm[];
    uint4* s_wc = (uint4*)sm;
    float* s_h  = (float*)(sm + OFF_H);     // [2][16][HSTR]
    float* s_gh = (float*)(sm + OFF_GH);    // [16][GSTR]
    unsigned char* s_rst = (unsigned char*)(sm + OFF_RST);  // [16][TT]

    const int tid  = threadIdx.x;
    const int q    = blockIdx.x & 1;
    const int b0   = (blockIdx.x >> 1) * 16;
    const int w    = tid >> 5;
    const int lane = tid & 31;
    const int tk   = lane & 3;
    const int g    = lane >> 2;
    // gate-phase role
    const int ug   = tid & 127;
    const int rg   = tid >> 7;
    const int r0   = rg * 8;
    const int gu   = q * 128 + ug;

    // fill SMEM weight cache: kc = 0..KCC-1 for this q (contiguous in g_Wm)
    {
        const uint4* src = (const uint4*)g_Wm + (size_t)q * (32 * 8 * 32 * 3);
        for (int i = tid; i < SW_U4; i += 256) s_wc[i] = src[i];
    }
    for (int i = tid; i < 16 * TT; i += 256) {
        int r = i >> 8, t = i & 255;
        s_rst[i] = (unsigned char)(is_init[(b0 + r) * TT + t] != 0);
    }
    // init h buffer 0 (t=0 masked hx)
    for (int i = tid; i < 16 * HID; i += 256) {
        int r = i >> 8, k = i & 255;
        float h = (is_init[(b0 + r) * TT] != 0) ? 0.f : hx[(size_t)(b0 + r) * HID + k];
        s_h[r * HSTR + k] = h;
    }
    __syncthreads();

    const float bhr = b_hh[gu], bhz = b_hh[256 + gu], bhn = b_hh[512 + gu];

    uint32_t my_h;
    asm("{ .reg .u64 t0; cvta.to.shared.u64 t0, %1; cvt.u32.u64 %0, t0; }"
        : "=r"(my_h) : "l"(s_h));
    uint32_t peer_h;
    asm("mapa.shared::cluster.u32 %0, %1, %2;"
        : "=r"(peer_h) : "r"(my_h), "r"(q ^ 1));

    for (int t = 0; t < TT; t++) {
        const int rb = t & 1, wb = rb ^ 1;
        const int hb = rb * 16 * HSTR;

        // prefetch input-side gates for gate phase (consumed after mma)
        float gxr[8], gxz[8], gxn[8];
        #pragma unroll
        for (int r = 0; r < 8; r++) {
            const float* gp = g_gx + ((size_t)(b0 + r0 + r) * TT + t) * G3;
            gxr[r] = gp[gu]; gxz[r] = gp[256 + gu]; gxn[r] = gp[512 + gu];
        }

        // ---- mma phase ----
        float cc[24];
        #pragma unroll
        for (int i = 0; i < 24; i++) cc[i] = 0.f;

        uint4 bufA[3], bufB[3], bufC[3];
        LDGB(bufC, 31);
        LDGB(bufA, KCC);
        LDGB(bufB, KCC + 1);

        // cached k-chunks
        #pragma unroll 1
        for (int kc = 0; kc < KCC; kc++) {
            uint4 bu[3];
            const uint4* p = s_wc + ((kc * 8 + w) * 32 + lane) * 3;
            bu[0] = p[0]; bu[1] = p[1]; bu[2] = p[2];
            COMPUTE_KC(bu, kc);
        }
        // streamed k-chunks 13..28 (pairs), then 29,30,31
        #pragma unroll 1
        for (int kc = KCC; kc <= 27; kc += 2) {
            COMPUTE_KC(bufA, kc);
            LDGB(bufA, kc + 2);
            COMPUTE_KC(bufB, kc + 1);
            LDGB(bufB, kc + 3);
        }
        COMPUTE_KC(bufA, 29);
        COMPUTE_KC(bufB, 30);
        COMPUTE_KC(bufC, 31);

        // store accumulators to s_gh
        #pragma unroll
        for (int j = 0; j < 6; j++) {
            int col0 = w * 48 + j * 8 + 2 * tk;
            *(float2*)&s_gh[g * GSTR + col0]       = make_float2(cc[4 * j],     cc[4 * j + 1]);
            *(float2*)&s_gh[(g + 8) * GSTR + col0] = make_float2(cc[4 * j + 2], cc[4 * j + 3]);
        }
        __syncthreads();

        // ---- gate phase (fp32) ----
        float hnew[8];
        #pragma unroll
        for (int r = 0; r < 8; r++) {
            int row = r0 + r;
            float ghr = s_gh[row * GSTR + ug];
            float ghz = s_gh[row * GSTR + 128 + ug];
            float ghn = s_gh[row * GSTR + 256 + ug];
            float hp  = s_h[hb + row * HSTR + gu];
            float rr = siga(gxr[r] + ghr + bhr);
            float zz = siga(gxz[r] + ghz + bhz);
            float nn = tanha(gxn[r] + rr * (ghn + bhn));
            hnew[r] = nn + zz * (hp - nn);
        }

        if (t == TT - 1) {
            #pragma unroll
            for (int r = 0; r < 8; r++) {
                g_seq[((size_t)(b0 + r0 + r) * TT + t) * HID + gu] = hnew[r];
                h_final[(size_t)(b0 + r0 + r) * HID + gu] = hnew[r];
            }
            break;
        }

        // write (t+1)-masked h: local + peer DSMEM; overlap g_seq w/ barrier
        #pragma unroll
        for (int r = 0; r < 8; r++) {
            int row = r0 + r;
            float v = s_rst[row * TT + t + 1] ? 0.f : hnew[r];
            s_h[wb * 16 * HSTR + row * HSTR + gu] = v;
            uint32_t off = (uint32_t)((wb * 16 * HSTR + row * HSTR + gu) * 4);
            asm volatile("st.shared::cluster.b32 [%0], %1;"
                         :: "r"(peer_h + off), "f"(v) : "memory");
        }
        asm volatile("barrier.cluster.arrive.aligned;" ::: "memory");
        #pragma unroll
        for (int r = 0; r < 8; r++)
            g_seq[((size_t)(b0 + r0 + r) * TT + t) * HID + gu] = hnew[r];
        asm volatile("barrier.cluster.wait.aligned;" ::: "memory");
    }
}

// ---- post: out = mish(seq) @ W_out + b_out, W_out in SMEM ------------------
__global__ __launch_bounds__(256) void post_kernel(
    const float* __restrict__ W_out, const float* __restrict__ b_out,
    float* __restrict__ out)
{
    __shared__ float s_m2[HID][32];
    __shared__ float s_w[HID * LAT];

    const int tid = threadIdx.x;
    const size_t row0 = (size_t)blockIdx.x * 32;

    for (int i = tid; i < HID * LAT; i += 256) s_w[i] = W_out[i];
    {
        const int row = tid & 31;
        const int kc  = (tid >> 5) * 32;
        const float* src = g_seq + (row0 + row) * HID + kc;
        #pragma unroll
        for (int c = 0; c < 8; c++) {
            float4 v = *(const float4*)(src + 4 * c);
            float hv[4] = {v.x, v.y, v.z, v.w};
            #pragma unroll
            for (int e = 0; e < 4; e++) {
                float h = hv[e];
                float sp = __logf(1.f + __expf(h));
                s_m2[kc + 4 * c + e][row] = h * tanha(sp);
            }
        }
    }
    __syncthreads();

    if (tid < 192) {
        const int pg = tid / 24;
        const int l  = tid - pg * 24;
        float2 a0 = make_float2(0.f, 0.f), a1 = make_float2(0.f, 0.f);
        #pragma unroll 4
        for (int k = 0; k < HID; k++) {
            float4 m4 = *(const float4*)&s_m2[k][4 * pg];
            float w = s_w[k * LAT + l];
            float2 w2 = make_float2(w, w);
            fma2(a0, w2, make_float2(m4.x, m4.y));
            fma2(a1, w2, make_float2(m4.z, m4.w));
        }
        const float bl = b_out[l];
        out[(row0 + 4 * pg + 0) * LAT + l] = a0.x + bl;
        out[(row0 + 4 * pg + 1) * LAT + l] = a0.y + bl;
        out[(row0 + 4 * pg + 2) * LAT + l] = a1.x + bl;
        out[(row0 + 4 * pg + 3) * LAT + l] = a1.y + bl;
    }
}

// ---------------------------------------------------------------------------
extern "C" void kernel_launch(void* const* d_in, const int* in_sizes, int n_in,
                              void* d_out, int out_size) {
    const float* obs     = (const float*)d_in[0];
    const int*   is_init = (const int*)  d_in[1];
    const float* hx      = (const float*)d_in[2];
    const float* W_in    = (const float*)d_in[3];
    const float* b_in    = (const float*)d_in[4];
    const float* W_ih    = (const float*)d_in[5];
    const float* b_ih    = (const float*)d_in[6];
    const float* W_hh    = (const float*)d_in[7];
    const float* b_hh    = (const float*)d_in[8];
    const float* W_out   = (const float*)d_in[9];
    const float* b_out   = (const float*)d_in[10];

    float* out     = (float*)d_out;                 // [B,T,LAT]
    float* h_final = out + (size_t)BB * TT * LAT;   // [B,HID]

    cudaFuncSetAttribute(rec_kernel,
                         cudaFuncAttributeMaxDynamicSharedMemorySize, REC_SMEM);

    trm_kernel<<<98304 / 256, 256>>>(W_hh);
    pre_kernel<<<(BB * TT) / 32, 256>>>(obs, W_in, b_in, W_ih, b_ih);
    rec_kernel<<<128, 256, REC_SMEM>>>(is_init, hx, b_hh, h_final);
    post_kernel<<<(BB * TT) / 32, 256>>>(W_out, b_out, out);
}

// round 12
// speedup vs baseline: 2.3379x; 1.3975x over previous
#include <cuda_runtime.h>
#include <math.h>
#include <stdint.h>

#define OBS   128
#define PROJ  64
#define HID   256
#define LAT   24
#define BB    1024
#define TT    256
#define G3    768

// ---- device scratch --------------------------------------------------------
__device__ float g_gx [(size_t)BB * TT * G3];
__device__ float g_seq[(size_t)BB * TT * HID];
// W_hh bf16, mma b-frag order: [q][gate-plane p][(kc*8+w)*32+lane] uint4
// uint4 = {b0(half0), b1(half0), b0(half1), b1(half1)}
__device__ uint4 g_Wmb[2 * 3 * 4096];

// ---- helpers ---------------------------------------------------------------
__device__ __forceinline__ void fma2(float2& d, float2 a, float2 b) {
    unsigned long long& dd = reinterpret_cast<unsigned long long&>(d);
    asm("fma.rn.f32x2 %0, %1, %2, %0;"
        : "+l"(dd)
        : "l"(reinterpret_cast<const unsigned long long&>(a)),
          "l"(reinterpret_cast<const unsigned long long&>(b)));
}
__device__ __forceinline__ float tanha(float x) {
    float y; asm("tanh.approx.f32 %0, %1;" : "=f"(y) : "f"(x)); return y;
}
__device__ __forceinline__ float siga(float x) {
    return fmaf(0.5f, tanha(0.5f * x), 0.5f);
}
// pack two floats to bf16x2: lo = first arg (bits [15:0]), hi = second
__device__ __forceinline__ uint32_t pkbf(float lo, float hi) {
    uint32_t r; asm("cvt.rn.bf16x2.f32 %0, %1, %2;" : "=r"(r) : "f"(hi), "f"(lo));
    return r;
}

#define MMAB(cp, a0, a1, a2, a3, b0, b1)                                \
    asm("mma.sync.aligned.m16n8k16.row.col.f32.bf16.bf16.f32 "          \
        "{%0,%1,%2,%3}, {%4,%5,%6,%7}, {%8,%9}, {%0,%1,%2,%3};"         \
        : "+f"((cp)[0]), "+f"((cp)[1]), "+f"((cp)[2]), "+f"((cp)[3])    \
        : "r"(a0), "r"(a1), "r"(a2), "r"(a3), "r"(b0), "r"(b1))

// ---- trm: repack W_hh to bf16 mma b-frag stream order ----------------------
__global__ void trm_kernel(const float* __restrict__ W) {
    int gid = blockIdx.x * 256 + threadIdx.x;   // 24576
    if (gid >= 24576) return;
    int lane = gid & 31;
    int w  = (gid >> 5) & 7;
    int kc = (gid >> 8) & 15;
    int rest = gid >> 12;            // 0..5
    int p = rest % 3;                // gate plane
    int q = rest / 3;
    int g = lane >> 2, tk = lane & 3;
    int k0 = kc * 16 + 2 * tk;
    uint4 v;
    #pragma unroll
    for (int half = 0; half < 2; half++) {
        int gcol = p * 256 + q * 128 + 16 * w + half * 8 + g;
        uint32_t b0 = pkbf(W[(size_t)k0 * G3 + gcol],
                           W[(size_t)(k0 + 1) * G3 + gcol]);
        uint32_t b1 = pkbf(W[(size_t)(k0 + 8) * G3 + gcol],
                           W[(size_t)(k0 + 9) * G3 + gcol]);
        if (half == 0) { v.x = b0; v.y = b1; } else { v.z = b0; v.w = b1; }
    }
    g_Wmb[(q * 3 + p) * 4096 + (kc * 8 + w) * 32 + lane] = v;
}

// ---- pre (unchanged, proven) -----------------------------------------------
__global__ __launch_bounds__(256) void pre_kernel(
    const float* __restrict__ obs, const float* __restrict__ W_in,
    const float* __restrict__ b_in, const float* __restrict__ W_ih,
    const float* __restrict__ b_ih)
{
    __shared__ float s_obsT[OBS][34];
    __shared__ float s_x2[PROJ][34];

    const int tid = threadIdx.x;
    const size_t row0 = (size_t)blockIdx.x * 32;

    for (int i = tid; i < 32 * OBS; i += 256) {
        int r = i >> 7, k = i & 127;
        s_obsT[k][r] = obs[(row0 + r) * OBS + k];
    }
    __syncthreads();

    {
        const int p = tid & 63, rh = tid >> 6;
        const float bi = b_in[p];
        float2 acc[4];
        #pragma unroll
        for (int pr = 0; pr < 4; pr++) acc[pr] = make_float2(bi, bi);
        #pragma unroll 4
        for (int k = 0; k < OBS; k++) {
            float w = W_in[k * PROJ + p];
            float2 w2 = make_float2(w, w);
            #pragma unroll
            for (int pr = 0; pr < 4; pr++)
                fma2(acc[pr], w2, *(const float2*)&s_obsT[k][8 * rh + 2 * pr]);
        }
        #pragma unroll
        for (int pr = 0; pr < 4; pr++) {
            s_x2[p][8 * rh + 2 * pr]     = acc[pr].x;
            s_x2[p][8 * rh + 2 * pr + 1] = acc[pr].y;
        }
    }
    __syncthreads();

    const int j = tid;
    const float bh0 = b_ih[j], bh1 = b_ih[j + 256], bh2 = b_ih[j + 512];
    for (int rt = 0; rt < 2; rt++) {
        float2 a0[8], a1[8], a2[8];
        #pragma unroll
        for (int pr = 0; pr < 8; pr++) {
            a0[pr] = make_float2(bh0, bh0);
            a1[pr] = make_float2(bh1, bh1);
            a2[pr] = make_float2(bh2, bh2);
        }
        #pragma unroll 2
        for (int p = 0; p < PROJ; p++) {
            float w0 = W_ih[p * G3 + j];
            float w1 = W_ih[p * G3 + j + 256];
            float w2 = W_ih[p * G3 + j + 512];
            float2 w02 = make_float2(w0, w0);
            float2 w12 = make_float2(w1, w1);
            float2 w22 = make_float2(w2, w2);
            #pragma unroll
            for (int pr = 0; pr < 8; pr++) {
                float2 xv = *(const float2*)&s_x2[p][16 * rt + 2 * pr];
                fma2(a0[pr], w02, xv);
                fma2(a1[pr], w12, xv);
                fma2(a2[pr], w22, xv);
            }
        }
        #pragma unroll
        for (int pr = 0; pr < 8; pr++) {
            size_t r = row0 + rt * 16 + 2 * pr;
            g_gx[r * G3 + j]             = a0[pr].x;
            g_gx[(r + 1) * G3 + j]       = a0[pr].y;
            g_gx[r * G3 + j + 256]       = a1[pr].x;
            g_gx[(r + 1) * G3 + j + 256] = a1[pr].y;
            g_gx[r * G3 + j + 512]       = a2[pr].x;
            g_gx[(r + 1) * G3 + j + 512] = a2[pr].y;
        }
    }
}

// ---- rec: cluster-2 scan, bf16 mma, all weights in SMEM --------------------
// 64 clusters x 2 CTAs x 256 thr. Cluster c: rows 16c..16c+15.
// CTA q: gh cols for units q*128..+127, all 3 gates.
// Warp w owns unit cols 16w..16w+15; tiles = gate(3) x half(2).
// Thread cells: rows {g, g+8} x cols {16w+2tk, +1, 16w+8+2tk, +1}.
// Gates computed in fragment layout (no SMEM exchange); h_prev in registers.
// s_hb: bf16 h, [2 buf][16 rows][264 stride] (u32 stride 132 == 4 mod 32).

#define HBS   264                         // bf16 row stride
#define OFF_HB  196608                    // after 192 KB weights
#define OFF_RST (OFF_HB + 2 * 16 * HBS * 2)   // +16896 = 213504
#define REC_SMEM (OFF_RST + 16 * TT)          // 217600

__global__ __launch_bounds__(256, 1) __cluster_dims__(2, 1, 1)
void rec_kernel(const int* __restrict__ is_init, const float* __restrict__ hx,
                const float* __restrict__ b_hh, float* __restrict__ h_final)
{
    extern __shared__ char sm[];
    uint4* s_wb = (uint4*)sm;                         // 12288 uint4 (3 planes)
    uint32_t* s_h32 = (uint32_t*)(sm + OFF_HB);       // bf16x2 view of s_hb
    unsigned char* s_rst = (unsigned char*)(sm + OFF_RST);

    const int tid  = threadIdx.x;
    const int q    = blockIdx.x & 1;
    const int b0c  = (blockIdx.x >> 1) * 16;
    const int w    = tid >> 5;
    const int lane = tid & 31;
    const int g    = lane >> 2;
    const int tk   = lane & 3;
    const int qb   = q * 128;

    // cache this CTA's full weight half (192 KB)
    {
        const uint4* src = g_Wmb + (size_t)q * 12288;
        for (int i = tid; i < 12288; i += 256) s_wb[i] = src[i];
    }
    for (int i = tid; i < 16 * TT; i += 256)
        s_rst[i] = (unsigned char)(is_init[(b0c + (i >> 8)) * TT + (i & 255)] != 0);
    // init s_hb buffer 0: t=0-masked hx, bf16 packed (all 128 u32 cols)
    for (int i = tid; i < 16 * 128; i += 256) {
        int r = i >> 7, kp = i & 127;
        bool m = (is_init[(b0c + r) * TT] != 0);
        float f0 = m ? 0.f : hx[(size_t)(b0c + r) * HID + 2 * kp];
        float f1 = m ? 0.f : hx[(size_t)(b0c + r) * HID + 2 * kp + 1];
        s_h32[r * 132 + kp] = pkbf(f0, f1);
    }

    // per-thread rows, biases, h_prev registers
    const int brow[2] = { b0c + g, b0c + g + 8 };
    float bh[3][4];
    #pragma unroll
    for (int gate = 0; gate < 3; gate++)
        #pragma unroll
        for (int hf = 0; hf < 2; hf++) {
            int c0 = gate * 256 + qb + 16 * w + hf * 8 + 2 * tk;
            bh[gate][hf * 2]     = b_hh[c0];
            bh[gate][hf * 2 + 1] = b_hh[c0 + 1];
        }
    float hprev[2][4];
    #pragma unroll
    for (int rw = 0; rw < 2; rw++) {
        bool m = (is_init[brow[rw] * TT] != 0);
        #pragma unroll
        for (int hf = 0; hf < 2; hf++) {
            int u = 16 * w + hf * 8 + 2 * tk;
            hprev[rw][hf * 2]     = m ? 0.f : hx[(size_t)brow[rw] * HID + qb + u];
            hprev[rw][hf * 2 + 1] = m ? 0.f : hx[(size_t)brow[rw] * HID + qb + u + 1];
        }
    }

    __syncthreads();
    asm volatile("barrier.cluster.arrive.aligned;" ::: "memory");
    asm volatile("barrier.cluster.wait.aligned;" ::: "memory");

    uint32_t my_hb;
    asm("{ .reg .u64 t0; cvta.to.shared.u64 t0, %1; cvt.u32.u64 %0, t0; }"
        : "=r"(my_hb) : "l"(s_h32));
    uint32_t peer_hb;
    asm("mapa.shared::cluster.u32 %0, %1, %2;"
        : "=r"(peer_hb) : "r"(my_hb), "r"(q ^ 1));

    for (int t = 0; t < TT; t++) {
        const int rb = t & 1, wbuf = rb ^ 1;
        const int hbase = rb * 2112;    // u32 buffer offset

        // gx prefetch (fp32): [gate][rw*2+hf] float2 = cols (2tk, 2tk+1)
        float2 gxv[3][4];
        #pragma unroll
        for (int rw = 0; rw < 2; rw++) {
            const float* gp = g_gx + ((size_t)brow[rw] * TT + t) * G3 + qb + 16 * w;
            #pragma unroll
            for (int gate = 0; gate < 3; gate++) {
                gxv[gate][rw * 2]     = *(const float2*)(gp + gate * 256 + 2 * tk);
                gxv[gate][rw * 2 + 1] = *(const float2*)(gp + gate * 256 + 8 + 2 * tk);
            }
        }

        // ---- mma: 16 k-chunks, all operands from SMEM ----
        float accs[6][4];
        #pragma unroll
        for (int i = 0; i < 6; i++)
            #pragma unroll
            for (int e = 0; e < 4; e++) accs[i][e] = 0.f;

        #pragma unroll 4
        for (int kc = 0; kc < 16; kc++) {
            uint4 br = s_wb[(kc * 8 + w) * 32 + lane];
            uint4 bz = s_wb[4096 + (kc * 8 + w) * 32 + lane];
            uint4 bn = s_wb[8192 + (kc * 8 + w) * 32 + lane];
            uint32_t a0 = s_h32[hbase + g * 132 + kc * 8 + tk];
            uint32_t a1 = s_h32[hbase + (g + 8) * 132 + kc * 8 + tk];
            uint32_t a2 = s_h32[hbase + g * 132 + kc * 8 + tk + 4];
            uint32_t a3 = s_h32[hbase + (g + 8) * 132 + kc * 8 + tk + 4];
            MMAB(accs[0], a0, a1, a2, a3, br.x, br.y);
            MMAB(accs[1], a0, a1, a2, a3, br.z, br.w);
            MMAB(accs[2], a0, a1, a2, a3, bz.x, bz.y);
            MMAB(accs[3], a0, a1, a2, a3, bz.z, bz.w);
            MMAB(accs[4], a0, a1, a2, a3, bn.x, bn.y);
            MMAB(accs[5], a0, a1, a2, a3, bn.z, bn.w);
        }

        // ---- gates in fragment layout ----
        float hnew[2][4];
        #pragma unroll
        for (int rw = 0; rw < 2; rw++) {
            #pragma unroll
            for (int hf = 0; hf < 2; hf++) {
                float gxr0 = gxv[0][rw * 2 + hf].x, gxr1 = gxv[0][rw * 2 + hf].y;
                float gxz0 = gxv[1][rw * 2 + hf].x, gxz1 = gxv[1][rw * 2 + hf].y;
                float gxn0 = gxv[2][rw * 2 + hf].x, gxn1 = gxv[2][rw * 2 + hf].y;
                #pragma unroll
                for (int e = 0; e < 2; e++) {
                    int ce = hf * 2 + e;
                    int ai = rw * 2 + e;
                    float gxrv = e ? gxr1 : gxr0;
                    float gxzv = e ? gxz1 : gxz0;
                    float gxnv = e ? gxn1 : gxn0;
                    float rr = siga(gxrv + accs[0 + hf][ai] + bh[0][ce]);
                    float zz = siga(gxzv + accs[2 + hf][ai] + bh[1][ce]);
                    float nn = tanha(gxnv + rr * (accs[4 + hf][ai] + bh[2][ce]));
                    hnew[rw][ce] = nn + zz * (hprev[rw][ce] - nn);
                }
            }
        }

        if (t == TT - 1) {
            #pragma unroll
            for (int rw = 0; rw < 2; rw++)
                #pragma unroll
                for (int hf = 0; hf < 2; hf++) {
                    int u = qb + 16 * w + hf * 8 + 2 * tk;
                    float2 v = make_float2(hnew[rw][hf * 2], hnew[rw][hf * 2 + 1]);
                    *(float2*)&g_seq[((size_t)brow[rw] * TT + t) * HID + u] = v;
                    *(float2*)&h_final[(size_t)brow[rw] * HID + u] = v;
                }
            break;
        }

        // ---- masked h write (bf16, local + peer) + update hprev ----
        // u32 col = (qb + 16w + hf*8 + 2tk)/2 = 64q + 8w + 4hf + tk  (q offset!)
        #pragma unroll
        for (int rw = 0; rw < 2; rw++) {
            int row = g + 8 * rw;
            bool mb = (s_rst[row * TT + t + 1] != 0);
            #pragma unroll
            for (int hf = 0; hf < 2; hf++) {
                float m0 = mb ? 0.f : hnew[rw][hf * 2];
                float m1 = mb ? 0.f : hnew[rw][hf * 2 + 1];
                uint32_t pk = pkbf(m0, m1);
                uint32_t idx = wbuf * 2112 + row * 132 + 64 * q + 8 * w + hf * 4 + tk;
                s_h32[idx] = pk;
                asm volatile("st.shared::cluster.b32 [%0], %1;"
                             :: "r"(peer_hb + idx * 4), "r"(pk) : "memory");
                hprev[rw][hf * 2]     = m0;
                hprev[rw][hf * 2 + 1] = m1;
            }
        }

        asm volatile("barrier.cluster.arrive.aligned;" ::: "memory");
        // overlap g_seq stores with barrier
        #pragma unroll
        for (int rw = 0; rw < 2; rw++)
            #pragma unroll
            for (int hf = 0; hf < 2; hf++) {
                int u = qb + 16 * w + hf * 8 + 2 * tk;
                *(float2*)&g_seq[((size_t)brow[rw] * TT + t) * HID + u] =
                    make_float2(hnew[rw][hf * 2], hnew[rw][hf * 2 + 1]);
            }
        asm volatile("barrier.cluster.wait.aligned;" ::: "memory");
    }
}

// ---- post (unchanged) -------------------------------------------------------
__global__ __launch_bounds__(256) void post_kernel(
    const float* __restrict__ W_out, const float* __restrict__ b_out,
    float* __restrict__ out)
{
    __shared__ float s_m2[HID][32];
    __shared__ float s_w[HID * LAT];

    const int tid = threadIdx.x;
    const size_t row0 = (size_t)blockIdx.x * 32;

    for (int i = tid; i < HID * LAT; i += 256) s_w[i] = W_out[i];
    {
        const int row = tid & 31;
        const int kc  = (tid >> 5) * 32;
        const float* src = g_seq + (row0 + row) * HID + kc;
        #pragma unroll
        for (int c = 0; c < 8; c++) {
            float4 v = *(const float4*)(src + 4 * c);
            float hv[4] = {v.x, v.y, v.z, v.w};
            #pragma unroll
            for (int e = 0; e < 4; e++) {
                float h = hv[e];
                float sp = __logf(1.f + __expf(h));
                s_m2[kc + 4 * c + e][row] = h * tanha(sp);
            }
        }
    }
    __syncthreads();

    if (tid < 192) {
        const int pg = tid / 24;
        const int l  = tid - pg * 24;
        float2 a0 = make_float2(0.f, 0.f), a1 = make_float2(0.f, 0.f);
        #pragma unroll 4
        for (int k = 0; k < HID; k++) {
            float4 m4 = *(const float4*)&s_m2[k][4 * pg];
            float w = s_w[k * LAT + l];
            float2 w2 = make_float2(w, w);
            fma2(a0, w2, make_float2(m4.x, m4.y));
            fma2(a1, w2, make_float2(m4.z, m4.w));
        }
        const float bl = b_out[l];
        out[(row0 + 4 * pg + 0) * LAT + l] = a0.x + bl;
        out[(row0 + 4 * pg + 1) * LAT + l] = a0.y + bl;
        out[(row0 + 4 * pg + 2) * LAT + l] = a1.x + bl;
        out[(row0 + 4 * pg + 3) * LAT + l] = a1.y + bl;
    }
}

// ---------------------------------------------------------------------------
extern "C" void kernel_launch(void* const* d_in, const int* in_sizes, int n_in,
                              void* d_out, int out_size) {
    const float* obs     = (const float*)d_in[0];
    const int*   is_init = (const int*)  d_in[1];
    const float* hx      = (const float*)d_in[2];
    const float* W_in    = (const float*)d_in[3];
    const float* b_in    = (const float*)d_in[4];
    const float* W_ih    = (const float*)d_in[5];
    const float* b_ih    = (const float*)d_in[6];
    const float* W_hh    = (const float*)d_in[7];
    const float* b_hh    = (const float*)d_in[8];
    const float* W_out   = (const float*)d_in[9];
    const float* b_out   = (const float*)d_in[10];

    float* out     = (float*)d_out;                 // [B,T,LAT]
    float* h_final = out + (size_t)BB * TT * LAT;   // [B,HID]

    cudaFuncSetAttribute(rec_kernel,
                         cudaFuncAttributeMaxDynamicSharedMemorySize, REC_SMEM);

    trm_kernel<<<96, 256>>>(W_hh);
    pre_kernel<<<(BB * TT) / 32, 256>>>(obs, W_in, b_in, W_ih, b_ih);
    rec_kernel<<<128, 256, REC_SMEM>>>(is_init, hx, b_hh, h_final);
    post_kernel<<<(BB * TT) / 32, 256>>>(W_out, b_out, out);
}

// round 14
// speedup vs baseline: 2.4381x; 1.0429x over previous
#include <cuda_runtime.h>
#include <math.h>
#include <stdint.h>

#define OBS   128
#define PROJ  64
#define HID   256
#define LAT   24
#define BB    1024
#define TT    256
#define G3    768

// ---- device scratch --------------------------------------------------------
__device__ float g_gx [(size_t)BB * TT * G3];
__device__ float g_seq[(size_t)BB * TT * HID];      // mish(h) per (b,t)
__device__ float g_x  [(size_t)BB * TT * PROJ];     // x = obs@W_in + b_in
// W_hh bf16 b-frag order (rec): [q][gate p][(kc*8+w)*32+lane] uint4
__device__ uint4 g_Wmb[2 * 3 * 4096];
// W_ih tf32 b-frag order (preB): [(grp*8+kc)*32+lane] uint4, grp = w*6+ch
__device__ uint4 g_Wihm[48 * 8 * 32];

// ---- helpers ---------------------------------------------------------------
__device__ __forceinline__ void fma2(float2& d, float2 a, float2 b) {
    unsigned long long& dd = reinterpret_cast<unsigned long long&>(d);
    asm("fma.rn.f32x2 %0, %1, %2, %0;"
        : "+l"(dd)
        : "l"(reinterpret_cast<const unsigned long long&>(a)),
          "l"(reinterpret_cast<const unsigned long long&>(b)));
}
__device__ __forceinline__ float tanha(float x) {
    float y; asm("tanh.approx.f32 %0, %1;" : "=f"(y) : "f"(x)); return y;
}
__device__ __forceinline__ float siga(float x) {
    return fmaf(0.5f, tanha(0.5f * x), 0.5f);
}
__device__ __forceinline__ float mishf(float h) {
    float sp = __logf(1.f + __expf(h));
    return h * tanha(sp);
}
__device__ __forceinline__ uint32_t pkbf(float lo, float hi) {
    uint32_t r; asm("cvt.rn.bf16x2.f32 %0, %1, %2;" : "=r"(r) : "f"(hi), "f"(lo));
    return r;
}
__device__ __forceinline__ uint32_t to_tf32(float f) {
    uint32_t r; asm("cvt.rna.tf32.f32 %0, %1;" : "=r"(r) : "f"(f)); return r;
}

#define MMAB(cp, a0, a1, a2, a3, b0, b1)                                \
    asm("mma.sync.aligned.m16n8k16.row.col.f32.bf16.bf16.f32 "          \
        "{%0,%1,%2,%3}, {%4,%5,%6,%7}, {%8,%9}, {%0,%1,%2,%3};"         \
        : "+f"((cp)[0]), "+f"((cp)[1]), "+f"((cp)[2]), "+f"((cp)[3])    \
        : "r"(a0), "r"(a1), "r"(a2), "r"(a3), "r"(b0), "r"(b1))

#define MMAT(cp, a0, a1, a2, a3, b0, b1)                                \
    asm("mma.sync.aligned.m16n8k8.row.col.f32.tf32.tf32.f32 "           \
        "{%0,%1,%2,%3}, {%4,%5,%6,%7}, {%8,%9}, {%0,%1,%2,%3};"         \
        : "+f"((cp)[0]), "+f"((cp)[1]), "+f"((cp)[2]), "+f"((cp)[3])    \
        : "r"(a0), "r"(a1), "r"(a2), "r"(a3), "r"(b0), "r"(b1))

// ---- trm: W_hh -> bf16 b-frag order (unchanged, proven) --------------------
__global__ void trm_kernel(const float* __restrict__ W) {
    int gid = blockIdx.x * 256 + threadIdx.x;   // 24576
    if (gid >= 24576) return;
    int lane = gid & 31;
    int w  = (gid >> 5) & 7;
    int kc = (gid >> 8) & 15;
    int rest = gid >> 12;
    int p = rest % 3, q = rest / 3;
    int g = lane >> 2, tk = lane & 3;
    int k0 = kc * 16 + 2 * tk;
    uint4 v;
    #pragma unroll
    for (int half = 0; half < 2; half++) {
        int gcol = p * 256 + q * 128 + 16 * w + half * 8 + g;
        uint32_t b0 = pkbf(W[(size_t)k0 * G3 + gcol],
                           W[(size_t)(k0 + 1) * G3 + gcol]);
        uint32_t b1 = pkbf(W[(size_t)(k0 + 8) * G3 + gcol],
                           W[(size_t)(k0 + 9) * G3 + gcol]);
        if (half == 0) { v.x = b0; v.y = b1; } else { v.z = b0; v.w = b1; }
    }
    g_Wmb[(q * 3 + p) * 4096 + (kc * 8 + w) * 32 + lane] = v;
}

// ---- trmi: W_ih -> tf32 b-frag order for preB ------------------------------
__global__ void trmi_kernel(const float* __restrict__ W) {
    int gid = blockIdx.x * 256 + threadIdx.x;   // 12288
    if (gid >= 12288) return;
    int lane = gid & 31;
    int kc = (gid >> 5) & 7;
    int grp = gid >> 8;                 // 0..47
    int g = lane >> 2, tk = lane & 3;
    int n0 = grp * 16;
    uint4 v;
    v.x = to_tf32(W[(size_t)(kc * 8 + tk) * G3 + n0 + g]);
    v.y = to_tf32(W[(size_t)(kc * 8 + tk + 4) * G3 + n0 + g]);
    v.z = to_tf32(W[(size_t)(kc * 8 + tk) * G3 + n0 + 8 + g]);
    v.w = to_tf32(W[(size_t)(kc * 8 + tk + 4) * G3 + n0 + 8 + g]);
    g_Wihm[gid] = v;
}

// ---- preA: x = obs@W_in + b_in -> g_x (FFMA2, 32 rows/CTA) -----------------
__global__ __launch_bounds__(256) void preA_kernel(
    const float* __restrict__ obs, const float* __restrict__ W_in,
    const float* __restrict__ b_in)
{
    __shared__ float s_obsT[OBS][34];
    const int tid = threadIdx.x;
    const size_t row0 = (size_t)blockIdx.x * 32;

    for (int i = tid; i < 32 * OBS; i += 256) {
        int r = i >> 7, k = i & 127;
        s_obsT[k][r] = obs[(row0 + r) * OBS + k];
    }
    __syncthreads();

    const int p = tid & 63, rh = tid >> 6;
    const float bi = b_in[p];
    float2 acc[4];
    #pragma unroll
    for (int pr = 0; pr < 4; pr++) acc[pr] = make_float2(bi, bi);
    #pragma unroll 4
    for (int k = 0; k < OBS; k++) {
        float w = W_in[k * PROJ + p];
        float2 w2 = make_float2(w, w);
        #pragma unroll
        for (int pr = 0; pr < 4; pr++)
            fma2(acc[pr], w2, *(const float2*)&s_obsT[k][8 * rh + 2 * pr]);
    }
    #pragma unroll
    for (int pr = 0; pr < 4; pr++) {
        g_x[(row0 + 8 * rh + 2 * pr) * PROJ + p]     = acc[pr].x;
        g_x[(row0 + 8 * rh + 2 * pr + 1) * PROJ + p] = acc[pr].y;
    }
}

// ---- preB: gx = x@W_ih + b_ih via tf32 mma, 64 rows/CTA --------------------
// warp w: cols 96w..96w+95 in 6 chunks of 16 (2 n8-tiles).
// s_x stride XS=68 >= PROJ; frag reads hit banks (4g+tk) -> conflict-free.
#define XS 68
__global__ __launch_bounds__(256) void preB_kernel(const float* __restrict__ b_ih)
{
    __shared__ float s_x[64 * XS];     // 17.4 KB

    const int tid  = threadIdx.x;
    const size_t row0 = (size_t)blockIdx.x * 64;
    const int w    = tid >> 5;
    const int lane = tid & 31;
    const int g    = lane >> 2;
    const int tk   = lane & 3;

    for (int i = tid; i < 64 * PROJ; i += 256) {
        int r = i >> 6, k = i & 63;
        s_x[r * XS + k] = g_x[(row0 + r) * PROJ + k];
    }
    __syncthreads();

    #pragma unroll 1
    for (int ch = 0; ch < 6; ch++) {
        const int n0 = 96 * w + 16 * ch;
        uint4 bb[8];
        #pragma unroll
        for (int kc = 0; kc < 8; kc++)
            bb[kc] = g_Wihm[(((w * 6 + ch) * 8) + kc) * 32 + lane];
        float2 bj0 = *(const float2*)&b_ih[n0 + 2 * tk];
        float2 bj1 = *(const float2*)&b_ih[n0 + 8 + 2 * tk];
        float acc[4][2][4];
        #pragma unroll
        for (int mt = 0; mt < 4; mt++) {
            acc[mt][0][0] = bj0.x; acc[mt][0][1] = bj0.y;
            acc[mt][0][2] = bj0.x; acc[mt][0][3] = bj0.y;
            acc[mt][1][0] = bj1.x; acc[mt][1][1] = bj1.y;
            acc[mt][1][2] = bj1.x; acc[mt][1][3] = bj1.y;
        }
        #pragma unroll
        for (int kc = 0; kc < 8; kc++) {
            #pragma unroll
            for (int mt = 0; mt < 4; mt++) {
                int base = (16 * mt + g) * XS + 8 * kc + tk;
                uint32_t a0 = to_tf32(s_x[base]);
                uint32_t a1 = to_tf32(s_x[base + 8 * XS]);
                uint32_t a2 = to_tf32(s_x[base + 4]);
                uint32_t a3 = to_tf32(s_x[base + 8 * XS + 4]);
                MMAT(acc[mt][0], a0, a1, a2, a3, bb[kc].x, bb[kc].y);
                MMAT(acc[mt][1], a0, a1, a2, a3, bb[kc].z, bb[kc].w);
            }
        }
        #pragma unroll
        for (int mt = 0; mt < 4; mt++) {
            size_t r1 = row0 + 16 * mt + g;
            #pragma unroll
            for (int j = 0; j < 2; j++) {
                int c0 = n0 + 8 * j + 2 * tk;
                *(float2*)&g_gx[r1 * G3 + c0] =
                    make_float2(acc[mt][j][0], acc[mt][j][1]);
                *(float2*)&g_gx[(r1 + 8) * G3 + c0] =
                    make_float2(acc[mt][j][2], acc[mt][j][3]);
            }
        }
    }
}

// ---- rec: cluster-2 scan, bf16 mma, all weights in SMEM (R12 + mish) -------
#define HBS   264
#define OFF_HB  196608
#define OFF_RST (OFF_HB + 2 * 16 * HBS * 2)
#define REC_SMEM (OFF_RST + 16 * TT)

__global__ __launch_bounds__(256, 1) __cluster_dims__(2, 1, 1)
void rec_kernel(const int* __restrict__ is_init, const float* __restrict__ hx,
                const float* __restrict__ b_hh, float* __restrict__ h_final)
{
    extern __shared__ char sm[];
    uint4* s_wb = (uint4*)sm;
    uint32_t* s_h32 = (uint32_t*)(sm + OFF_HB);
    unsigned char* s_rst = (unsigned char*)(sm + OFF_RST);

    const int tid  = threadIdx.x;
    const int q    = blockIdx.x & 1;
    const int b0c  = (blockIdx.x >> 1) * 16;
    const int w    = tid >> 5;
    const int lane = tid & 31;
    const int g    = lane >> 2;
    const int tk   = lane & 3;
    const int qb   = q * 128;

    {
        const uint4* src = g_Wmb + (size_t)q * 12288;
        for (int i = tid; i < 12288; i += 256) s_wb[i] = src[i];
    }
    for (int i = tid; i < 16 * TT; i += 256)
        s_rst[i] = (unsigned char)(is_init[(b0c + (i >> 8)) * TT + (i & 255)] != 0);
    for (int i = tid; i < 16 * 128; i += 256) {
        int r = i >> 7, kp = i & 127;
        bool m = (is_init[(b0c + r) * TT] != 0);
        float f0 = m ? 0.f : hx[(size_t)(b0c + r) * HID + 2 * kp];
        float f1 = m ? 0.f : hx[(size_t)(b0c + r) * HID + 2 * kp + 1];
        s_h32[r * 132 + kp] = pkbf(f0, f1);
    }

    const int brow[2] = { b0c + g, b0c + g + 8 };
    float bh[3][4];
    #pragma unroll
    for (int gate = 0; gate < 3; gate++)
        #pragma unroll
        for (int hf = 0; hf < 2; hf++) {
            int c0 = gate * 256 + qb + 16 * w + hf * 8 + 2 * tk;
            bh[gate][hf * 2]     = b_hh[c0];
            bh[gate][hf * 2 + 1] = b_hh[c0 + 1];
        }
    float hprev[2][4];
    #pragma unroll
    for (int rw = 0; rw < 2; rw++) {
        bool m = (is_init[brow[rw] * TT] != 0);
        #pragma unroll
        for (int hf = 0; hf < 2; hf++) {
            int u = 16 * w + hf * 8 + 2 * tk;
            hprev[rw][hf * 2]     = m ? 0.f : hx[(size_t)brow[rw] * HID + qb + u];
            hprev[rw][hf * 2 + 1] = m ? 0.f : hx[(size_t)brow[rw] * HID + qb + u + 1];
        }
    }

    __syncthreads();
    asm volatile("barrier.cluster.arrive.aligned;" ::: "memory");
    asm volatile("barrier.cluster.wait.aligned;" ::: "memory");

    uint32_t my_hb;
    asm("{ .reg .u64 t0; cvta.to.shared.u64 t0, %1; cvt.u32.u64 %0, t0; }"
        : "=r"(my_hb) : "l"(s_h32));
    uint32_t peer_hb;
    asm("mapa.shared::cluster.u32 %0, %1, %2;"
        : "=r"(peer_hb) : "r"(my_hb), "r"(q ^ 1));

    for (int t = 0; t < TT; t++) {
        const int rb = t & 1, wbuf = rb ^ 1;
        const int hbase = rb * 2112;

        float2 gxv[3][4];
        #pragma unroll
        for (int rw = 0; rw < 2; rw++) {
            const float* gp = g_gx + ((size_t)brow[rw] * TT + t) * G3 + qb + 16 * w;
            #pragma unroll
            for (int gate = 0; gate < 3; gate++) {
                gxv[gate][rw * 2]     = *(const float2*)(gp + gate * 256 + 2 * tk);
                gxv[gate][rw * 2 + 1] = *(const float2*)(gp + gate * 256 + 8 + 2 * tk);
            }
        }

        float accs[6][4];
        #pragma unroll
        for (int i = 0; i < 6; i++)
            #pragma unroll
            for (int e = 0; e < 4; e++) accs[i][e] = 0.f;

        #pragma unroll 4
        for (int kc = 0; kc < 16; kc++) {
            uint4 br = s_wb[(kc * 8 + w) * 32 + lane];
            uint4 bz = s_wb[4096 + (kc * 8 + w) * 32 + lane];
            uint4 bn = s_wb[8192 + (kc * 8 + w) * 32 + lane];
            uint32_t a0 = s_h32[hbase + g * 132 + kc * 8 + tk];
            uint32_t a1 = s_h32[hbase + (g + 8) * 132 + kc * 8 + tk];
            uint32_t a2 = s_h32[hbase + g * 132 + kc * 8 + tk + 4];
            uint32_t a3 = s_h32[hbase + (g + 8) * 132 + kc * 8 + tk + 4];
            MMAB(accs[0], a0, a1, a2, a3, br.x, br.y);
            MMAB(accs[1], a0, a1, a2, a3, br.z, br.w);
            MMAB(accs[2], a0, a1, a2, a3, bz.x, bz.y);
            MMAB(accs[3], a0, a1, a2, a3, bz.z, bz.w);
            MMAB(accs[4], a0, a1, a2, a3, bn.x, bn.y);
            MMAB(accs[5], a0, a1, a2, a3, bn.z, bn.w);
        }

        float hnew[2][4];
        #pragma unroll
        for (int rw = 0; rw < 2; rw++) {
            #pragma unroll
            for (int hf = 0; hf < 2; hf++) {
                float gxr0 = gxv[0][rw * 2 + hf].x, gxr1 = gxv[0][rw * 2 + hf].y;
                float gxz0 = gxv[1][rw * 2 + hf].x, gxz1 = gxv[1][rw * 2 + hf].y;
                float gxn0 = gxv[2][rw * 2 + hf].x, gxn1 = gxv[2][rw * 2 + hf].y;
                #pragma unroll
                for (int e = 0; e < 2; e++) {
                    int ce = hf * 2 + e;
                    int ai = rw * 2 + e;
                    float gxrv = e ? gxr1 : gxr0;
                    float gxzv = e ? gxz1 : gxz0;
                    float gxnv = e ? gxn1 : gxn0;
                    float rr = siga(gxrv + accs[0 + hf][ai] + bh[0][ce]);
                    float zz = siga(gxzv + accs[2 + hf][ai] + bh[1][ce]);
                    float nn = tanha(gxnv + rr * (accs[4 + hf][ai] + bh[2][ce]));
                    hnew[rw][ce] = nn + zz * (hprev[rw][ce] - nn);
                }
            }
        }

        if (t == TT - 1) {
            #pragma unroll
            for (int rw = 0; rw < 2; rw++)
                #pragma unroll
                for (int hf = 0; hf < 2; hf++) {
                    int u = qb + 16 * w + hf * 8 + 2 * tk;
                    *(float2*)&g_seq[((size_t)brow[rw] * TT + t) * HID + u] =
                        make_float2(mishf(hnew[rw][hf * 2]), mishf(hnew[rw][hf * 2 + 1]));
                    *(float2*)&h_final[(size_t)brow[rw] * HID + u] =
                        make_float2(hnew[rw][hf * 2], hnew[rw][hf * 2 + 1]);
                }
            break;
        }

        #pragma unroll
        for (int rw = 0; rw < 2; rw++) {
            int row = g + 8 * rw;
            bool mb = (s_rst[row * TT + t + 1] != 0);
            #pragma unroll
            for (int hf = 0; hf < 2; hf++) {
                float m0 = mb ? 0.f : hnew[rw][hf * 2];
                float m1 = mb ? 0.f : hnew[rw][hf * 2 + 1];
                uint32_t pk = pkbf(m0, m1);
                uint32_t idx = wbuf * 2112 + row * 132 + 64 * q + 8 * w + hf * 4 + tk;
                s_h32[idx] = pk;
                asm volatile("st.shared::cluster.b32 [%0], %1;"
                             :: "r"(peer_hb + idx * 4), "r"(pk) : "memory");
                hprev[rw][hf * 2]     = m0;
                hprev[rw][hf * 2 + 1] = m1;
            }
        }

        asm volatile("barrier.cluster.arrive.aligned;" ::: "memory");
        #pragma unroll
        for (int rw = 0; rw < 2; rw++)
            #pragma unroll
            for (int hf = 0; hf < 2; hf++) {
                int u = qb + 16 * w + hf * 8 + 2 * tk;
                *(float2*)&g_seq[((size_t)brow[rw] * TT + t) * HID + u] =
                    make_float2(mishf(hnew[rw][hf * 2]), mishf(hnew[rw][hf * 2 + 1]));
            }
        asm volatile("barrier.cluster.wait.aligned;" ::: "memory");
    }
}

// ---- post: out = g_seq @ W_out + b_out (mish precomputed in rec) -----------
__global__ __launch_bounds__(256) void post_kernel(
    const float* __restrict__ W_out, const float* __restrict__ b_out,
    float* __restrict__ out)
{
    __shared__ float s_m2[HID][32];
    __shared__ float s_w[HID * LAT];

    const int tid = threadIdx.x;
    const size_t row0 = (size_t)blockIdx.x * 32;

    for (int i = tid; i < HID * LAT; i += 256) s_w[i] = W_out[i];
    {
        const int row = tid & 31;
        const int kc  = (tid >> 5) * 32;
        const float* src = g_seq + (row0 + row) * HID + kc;
        #pragma unroll
        for (int c = 0; c < 8; c++) {
            float4 v = *(const float4*)(src + 4 * c);
            s_m2[kc + 4 * c + 0][row] = v.x;
            s_m2[kc + 4 * c + 1][row] = v.y;
            s_m2[kc + 4 * c + 2][row] = v.z;
            s_m2[kc + 4 * c + 3][row] = v.w;
        }
    }
    __syncthreads();

    if (tid < 192) {
        const int pg = tid / 24;
        const int l  = tid - pg * 24;
        float2 a0 = make_float2(0.f, 0.f), a1 = make_float2(0.f, 0.f);
        #pragma unroll 4
        for (int k = 0; k < HID; k++) {
            float4 m4 = *(const float4*)&s_m2[k][4 * pg];
            float w = s_w[k * LAT + l];
            float2 w2 = make_float2(w, w);
            fma2(a0, w2, make_float2(m4.x, m4.y));
            fma2(a1, w2, make_float2(m4.z, m4.w));
        }
        const float bl = b_out[l];
        out[(row0 + 4 * pg + 0) * LAT + l] = a0.x + bl;
        out[(row0 + 4 * pg + 1) * LAT + l] = a0.y + bl;
        out[(row0 + 4 * pg + 2) * LAT + l] = a1.x + bl;
        out[(row0 + 4 * pg + 3) * LAT + l] = a1.y + bl;
    }
}

// ---------------------------------------------------------------------------
extern "C" void kernel_launch(void* const* d_in, const int* in_sizes, int n_in,
                              void* d_out, int out_size) {
    const float* obs     = (const float*)d_in[0];
    const int*   is_init = (const int*)  d_in[1];
    const float* hx      = (const float*)d_in[2];
    const float* W_in    = (const float*)d_in[3];
    const float* b_in    = (const float*)d_in[4];
    const float* W_ih    = (const float*)d_in[5];
    const float* b_ih    = (const float*)d_in[6];
    const float* W_hh    = (const float*)d_in[7];
    const float* b_hh    = (const float*)d_in[8];
    const float* W_out   = (const float*)d_in[9];
    const float* b_out   = (const float*)d_in[10];

    float* out     = (float*)d_out;                 // [B,T,LAT]
    float* h_final = out + (size_t)BB * TT * LAT;   // [B,HID]

    cudaFuncSetAttribute(rec_kernel,
                         cudaFuncAttributeMaxDynamicSharedMemorySize, REC_SMEM);

    trm_kernel<<<96, 256>>>(W_hh);
    trmi_kernel<<<48, 256>>>(W_ih);
    preA_kernel<<<(BB * TT) / 32, 256>>>(obs, W_in, b_in);
    preB_kernel<<<(BB * TT) / 64, 256>>>(b_ih);
    rec_kernel<<<128, 256, REC_SMEM>>>(is_init, hx, b_hh, h_final);
    post_kernel<<<(BB * TT) / 32, 256>>>(W_out, b_out, out);
}

// round 15
// speedup vs baseline: 2.6996x; 1.1072x over previous
#include <cuda_runtime.h>
#include <math.h>
#include <stdint.h>

#define OBS   128
#define PROJ  64
#define HID   256
#define LAT   24
#define BB    1024
#define TT    256
#define G3    768

// ---- device scratch --------------------------------------------------------
__device__ float g_gx [(size_t)BB * TT * G3];
__device__ float g_seq[(size_t)BB * TT * HID];      // mish(h) per (b,t)
__device__ float g_x  [(size_t)BB * TT * PROJ];     // x = obs@W_in + b_in
// W_hh bf16 b-frag order (rec): [q][gate p][(kc*8+w)*32+lane] uint4
__device__ uint4 g_Wmb[2 * 3 * 4096];
// W_ih tf32 b-frag order (preB): [(grp*8+kc)*32+lane] uint4, grp = w*6+ch
__device__ uint4 g_Wihm[48 * 8 * 32];

// ---- helpers ---------------------------------------------------------------
__device__ __forceinline__ void fma2(float2& d, float2 a, float2 b) {
    unsigned long long& dd = reinterpret_cast<unsigned long long&>(d);
    asm("fma.rn.f32x2 %0, %1, %2, %0;"
        : "+l"(dd)
        : "l"(reinterpret_cast<const unsigned long long&>(a)),
          "l"(reinterpret_cast<const unsigned long long&>(b)));
}
__device__ __forceinline__ float tanha(float x) {
    float y; asm("tanh.approx.f32 %0, %1;" : "=f"(y) : "f"(x)); return y;
}
__device__ __forceinline__ float siga(float x) {
    return fmaf(0.5f, tanha(0.5f * x), 0.5f);
}
__device__ __forceinline__ float mishf(float h) {
    float sp = __logf(1.f + __expf(h));
    return h * tanha(sp);
}
__device__ __forceinline__ uint32_t pkbf(float lo, float hi) {
    uint32_t r; asm("cvt.rn.bf16x2.f32 %0, %1, %2;" : "=r"(r) : "f"(hi), "f"(lo));
    return r;
}
__device__ __forceinline__ uint32_t to_tf32(float f) {
    uint32_t r; asm("cvt.rna.tf32.f32 %0, %1;" : "=r"(r) : "f"(f)); return r;
}

#define MMAB(cp, a0, a1, a2, a3, b0, b1)                                \
    asm("mma.sync.aligned.m16n8k16.row.col.f32.bf16.bf16.f32 "          \
        "{%0,%1,%2,%3}, {%4,%5,%6,%7}, {%8,%9}, {%0,%1,%2,%3};"         \
        : "+f"((cp)[0]), "+f"((cp)[1]), "+f"((cp)[2]), "+f"((cp)[3])    \
        : "r"(a0), "r"(a1), "r"(a2), "r"(a3), "r"(b0), "r"(b1))

#define MMAT(cp, a0, a1, a2, a3, b0, b1)                                \
    asm("mma.sync.aligned.m16n8k8.row.col.f32.tf32.tf32.f32 "           \
        "{%0,%1,%2,%3}, {%4,%5,%6,%7}, {%8,%9}, {%0,%1,%2,%3};"         \
        : "+f"((cp)[0]), "+f"((cp)[1]), "+f"((cp)[2]), "+f"((cp)[3])    \
        : "r"(a0), "r"(a1), "r"(a2), "r"(a3), "r"(b0), "r"(b1))

// ---- trm: W_hh -> bf16 b-frag order (unchanged, proven) --------------------
__global__ void trm_kernel(const float* __restrict__ W) {
    int gid = blockIdx.x * 256 + threadIdx.x;   // 24576
    if (gid >= 24576) return;
    int lane = gid & 31;
    int w  = (gid >> 5) & 7;
    int kc = (gid >> 8) & 15;
    int rest = gid >> 12;
    int p = rest % 3, q = rest / 3;
    int g = lane >> 2, tk = lane & 3;
    int k0 = kc * 16 + 2 * tk;
    uint4 v;
    #pragma unroll
    for (int half = 0; half < 2; half++) {
        int gcol = p * 256 + q * 128 + 16 * w + half * 8 + g;
        uint32_t b0 = pkbf(W[(size_t)k0 * G3 + gcol],
                           W[(size_t)(k0 + 1) * G3 + gcol]);
        uint32_t b1 = pkbf(W[(size_t)(k0 + 8) * G3 + gcol],
                           W[(size_t)(k0 + 9) * G3 + gcol]);
        if (half == 0) { v.x = b0; v.y = b1; } else { v.z = b0; v.w = b1; }
    }
    g_Wmb[(q * 3 + p) * 4096 + (kc * 8 + w) * 32 + lane] = v;
}

// ---- trmi: W_ih -> tf32 b-frag order for preB ------------------------------
__global__ void trmi_kernel(const float* __restrict__ W) {
    int gid = blockIdx.x * 256 + threadIdx.x;   // 12288
    if (gid >= 12288) return;
    int lane = gid & 31;
    int kc = (gid >> 5) & 7;
    int grp = gid >> 8;                 // 0..47
    int g = lane >> 2, tk = lane & 3;
    int n0 = grp * 16;
    uint4 v;
    v.x = to_tf32(W[(size_t)(kc * 8 + tk) * G3 + n0 + g]);
    v.y = to_tf32(W[(size_t)(kc * 8 + tk + 4) * G3 + n0 + g]);
    v.z = to_tf32(W[(size_t)(kc * 8 + tk) * G3 + n0 + 8 + g]);
    v.w = to_tf32(W[(size_t)(kc * 8 + tk + 4) * G3 + n0 + 8 + g]);
    g_Wihm[gid] = v;
}

// ---- preA: x = obs@W_in + b_in -> g_x (FFMA2, 32 rows/CTA) -----------------
__global__ __launch_bounds__(256) void preA_kernel(
    const float* __restrict__ obs, const float* __restrict__ W_in,
    const float* __restrict__ b_in)
{
    __shared__ float s_obsT[OBS][34];
    const int tid = threadIdx.x;
    const size_t row0 = (size_t)blockIdx.x * 32;

    for (int i = tid; i < 32 * OBS; i += 256) {
        int r = i >> 7, k = i & 127;
        s_obsT[k][r] = obs[(row0 + r) * OBS + k];
    }
    __syncthreads();

    const int p = tid & 63, rh = tid >> 6;
    const float bi = b_in[p];
    float2 acc[4];
    #pragma unroll
    for (int pr = 0; pr < 4; pr++) acc[pr] = make_float2(bi, bi);
    #pragma unroll 4
    for (int k = 0; k < OBS; k++) {
        float w = W_in[k * PROJ + p];
        float2 w2 = make_float2(w, w);
        #pragma unroll
        for (int pr = 0; pr < 4; pr++)
            fma2(acc[pr], w2, *(const float2*)&s_obsT[k][8 * rh + 2 * pr]);
    }
    #pragma unroll
    for (int pr = 0; pr < 4; pr++) {
        g_x[(row0 + 8 * rh + 2 * pr) * PROJ + p]     = acc[pr].x;
        g_x[(row0 + 8 * rh + 2 * pr + 1) * PROJ + p] = acc[pr].y;
    }
}

// ---- preB: gx = x@W_ih + b_ih via tf32 mma, 32 rows/CTA, 2 CTA/SM ----------
// warp w: cols 96w..96w+95 in 6 chunks of 16 (2 n8-tiles), 2 m-tiles.
// s_x stride XS=68; frag reads hit banks (4g+tk) -> conflict-free.
#define XS 68
__global__ __launch_bounds__(256, 2) void preB_kernel(const float* __restrict__ b_ih)
{
    __shared__ float s_x[32 * XS];     // 8.7 KB

    const int tid  = threadIdx.x;
    const size_t row0 = (size_t)blockIdx.x * 32;
    const int w    = tid >> 5;
    const int lane = tid & 31;
    const int g    = lane >> 2;
    const int tk   = lane & 3;

    for (int i = tid; i < 32 * PROJ; i += 256) {
        int r = i >> 6, k = i & 63;
        s_x[r * XS + k] = g_x[(row0 + r) * PROJ + k];
    }
    __syncthreads();

    #pragma unroll 1
    for (int ch = 0; ch < 6; ch++) {
        const int n0 = 96 * w + 16 * ch;
        uint4 bb[8];
        #pragma unroll
        for (int kc = 0; kc < 8; kc++)
            bb[kc] = g_Wihm[(((w * 6 + ch) * 8) + kc) * 32 + lane];
        float2 bj0 = *(const float2*)&b_ih[n0 + 2 * tk];
        float2 bj1 = *(const float2*)&b_ih[n0 + 8 + 2 * tk];
        float acc[2][2][4];
        #pragma unroll
        for (int mt = 0; mt < 2; mt++) {
            acc[mt][0][0] = bj0.x; acc[mt][0][1] = bj0.y;
            acc[mt][0][2] = bj0.x; acc[mt][0][3] = bj0.y;
            acc[mt][1][0] = bj1.x; acc[mt][1][1] = bj1.y;
            acc[mt][1][2] = bj1.x; acc[mt][1][3] = bj1.y;
        }
        #pragma unroll
        for (int kc = 0; kc < 8; kc++) {
            #pragma unroll
            for (int mt = 0; mt < 2; mt++) {
                int base = (16 * mt + g) * XS + 8 * kc + tk;
                uint32_t a0 = to_tf32(s_x[base]);
                uint32_t a1 = to_tf32(s_x[base + 8 * XS]);
                uint32_t a2 = to_tf32(s_x[base + 4]);
                uint32_t a3 = to_tf32(s_x[base + 8 * XS + 4]);
                MMAT(acc[mt][0], a0, a1, a2, a3, bb[kc].x, bb[kc].y);
                MMAT(acc[mt][1], a0, a1, a2, a3, bb[kc].z, bb[kc].w);
            }
        }
        #pragma unroll
        for (int mt = 0; mt < 2; mt++) {
            size_t r1 = row0 + 16 * mt + g;
            #pragma unroll
            for (int j = 0; j < 2; j++) {
                int c0 = n0 + 8 * j + 2 * tk;
                *(float2*)&g_gx[r1 * G3 + c0] =
                    make_float2(acc[mt][j][0], acc[mt][j][1]);
                *(float2*)&g_gx[(r1 + 8) * G3 + c0] =
                    make_float2(acc[mt][j][2], acc[mt][j][3]);
            }
        }
    }
}

// ---- rec: cluster-2 scan, bf16 mma, all weights in SMEM (R14, proven) ------
#define HBS   264
#define OFF_HB  196608
#define OFF_RST (OFF_HB + 2 * 16 * HBS * 2)
#define REC_SMEM (OFF_RST + 16 * TT)

__global__ __launch_bounds__(256, 1) __cluster_dims__(2, 1, 1)
void rec_kernel(const int* __restrict__ is_init, const float* __restrict__ hx,
                const float* __restrict__ b_hh, float* __restrict__ h_final)
{
    extern __shared__ char sm[];
    uint4* s_wb = (uint4*)sm;
    uint32_t* s_h32 = (uint32_t*)(sm + OFF_HB);
    unsigned char* s_rst = (unsigned char*)(sm + OFF_RST);

    const int tid  = threadIdx.x;
    const int q    = blockIdx.x & 1;
    const int b0c  = (blockIdx.x >> 1) * 16;
    const int w    = tid >> 5;
    const int lane = tid & 31;
    const int g    = lane >> 2;
    const int tk   = lane & 3;
    const int qb   = q * 128;

    {
        const uint4* src = g_Wmb + (size_t)q * 12288;
        for (int i = tid; i < 12288; i += 256) s_wb[i] = src[i];
    }
    for (int i = tid; i < 16 * TT; i += 256)
        s_rst[i] = (unsigned char)(is_init[(b0c + (i >> 8)) * TT + (i & 255)] != 0);
    for (int i = tid; i < 16 * 128; i += 256) {
        int r = i >> 7, kp = i & 127;
        bool m = (is_init[(b0c + r) * TT] != 0);
        float f0 = m ? 0.f : hx[(size_t)(b0c + r) * HID + 2 * kp];
        float f1 = m ? 0.f : hx[(size_t)(b0c + r) * HID + 2 * kp + 1];
        s_h32[r * 132 + kp] = pkbf(f0, f1);
    }

    const int brow[2] = { b0c + g, b0c + g + 8 };
    float bh[3][4];
    #pragma unroll
    for (int gate = 0; gate < 3; gate++)
        #pragma unroll
        for (int hf = 0; hf < 2; hf++) {
            int c0 = gate * 256 + qb + 16 * w + hf * 8 + 2 * tk;
            bh[gate][hf * 2]     = b_hh[c0];
            bh[gate][hf * 2 + 1] = b_hh[c0 + 1];
        }
    float hprev[2][4];
    #pragma unroll
    for (int rw = 0; rw < 2; rw++) {
        bool m = (is_init[brow[rw] * TT] != 0);
        #pragma unroll
        for (int hf = 0; hf < 2; hf++) {
            int u = 16 * w + hf * 8 + 2 * tk;
            hprev[rw][hf * 2]     = m ? 0.f : hx[(size_t)brow[rw] * HID + qb + u];
            hprev[rw][hf * 2 + 1] = m ? 0.f : hx[(size_t)brow[rw] * HID + qb + u + 1];
        }
    }

    __syncthreads();
    asm volatile("barrier.cluster.arrive.aligned;" ::: "memory");
    asm volatile("barrier.cluster.wait.aligned;" ::: "memory");

    uint32_t my_hb;
    asm("{ .reg .u64 t0; cvta.to.shared.u64 t0, %1; cvt.u32.u64 %0, t0; }"
        : "=r"(my_hb) : "l"(s_h32));
    uint32_t peer_hb;
    asm("mapa.shared::cluster.u32 %0, %1, %2;"
        : "=r"(peer_hb) : "r"(my_hb), "r"(q ^ 1));

    for (int t = 0; t < TT; t++) {
        const int rb = t & 1, wbuf = rb ^ 1;
        const int hbase = rb * 2112;

        float2 gxv[3][4];
        #pragma unroll
        for (int rw = 0; rw < 2; rw++) {
            const float* gp = g_gx + ((size_t)brow[rw] * TT + t) * G3 + qb + 16 * w;
            #pragma unroll
            for (int gate = 0; gate < 3; gate++) {
                gxv[gate][rw * 2]     = *(const float2*)(gp + gate * 256 + 2 * tk);
                gxv[gate][rw * 2 + 1] = *(const float2*)(gp + gate * 256 + 8 + 2 * tk);
            }
        }

        float accs[6][4];
        #pragma unroll
        for (int i = 0; i < 6; i++)
            #pragma unroll
            for (int e = 0; e < 4; e++) accs[i][e] = 0.f;

        #pragma unroll 4
        for (int kc = 0; kc < 16; kc++) {
            uint4 br = s_wb[(kc * 8 + w) * 32 + lane];
            uint4 bz = s_wb[4096 + (kc * 8 + w) * 32 + lane];
            uint4 bn = s_wb[8192 + (kc * 8 + w) * 32 + lane];
            uint32_t a0 = s_h32[hbase + g * 132 + kc * 8 + tk];
            uint32_t a1 = s_h32[hbase + (g + 8) * 132 + kc * 8 + tk];
            uint32_t a2 = s_h32[hbase + g * 132 + kc * 8 + tk + 4];
            uint32_t a3 = s_h32[hbase + (g + 8) * 132 + kc * 8 + tk + 4];
            MMAB(accs[0], a0, a1, a2, a3, br.x, br.y);
            MMAB(accs[1], a0, a1, a2, a3, br.z, br.w);
            MMAB(accs[2], a0, a1, a2, a3, bz.x, bz.y);
            MMAB(accs[3], a0, a1, a2, a3, bz.z, bz.w);
            MMAB(accs[4], a0, a1, a2, a3, bn.x, bn.y);
            MMAB(accs[5], a0, a1, a2, a3, bn.z, bn.w);
        }

        float hnew[2][4];
        #pragma unroll
        for (int rw = 0; rw < 2; rw++) {
            #pragma unroll
            for (int hf = 0; hf < 2; hf++) {
                float gxr0 = gxv[0][rw * 2 + hf].x, gxr1 = gxv[0][rw * 2 + hf].y;
                float gxz0 = gxv[1][rw * 2 + hf].x, gxz1 = gxv[1][rw * 2 + hf].y;
                float gxn0 = gxv[2][rw * 2 + hf].x, gxn1 = gxv[2][rw * 2 + hf].y;
                #pragma unroll
                for (int e = 0; e < 2; e++) {
                    int ce = hf * 2 + e;
                    int ai = rw * 2 + e;
                    float gxrv = e ? gxr1 : gxr0;
                    float gxzv = e ? gxz1 : gxz0;
                    float gxnv = e ? gxn1 : gxn0;
                    float rr = siga(gxrv + accs[0 + hf][ai] + bh[0][ce]);
                    float zz = siga(gxzv + accs[2 + hf][ai] + bh[1][ce]);
                    float nn = tanha(gxnv + rr * (accs[4 + hf][ai] + bh[2][ce]));
                    hnew[rw][ce] = nn + zz * (hprev[rw][ce] - nn);
                }
            }
        }

        if (t == TT - 1) {
            #pragma unroll
            for (int rw = 0; rw < 2; rw++)
                #pragma unroll
                for (int hf = 0; hf < 2; hf++) {
                    int u = qb + 16 * w + hf * 8 + 2 * tk;
                    *(float2*)&g_seq[((size_t)brow[rw] * TT + t) * HID + u] =
                        make_float2(mishf(hnew[rw][hf * 2]), mishf(hnew[rw][hf * 2 + 1]));
                    *(float2*)&h_final[(size_t)brow[rw] * HID + u] =
                        make_float2(hnew[rw][hf * 2], hnew[rw][hf * 2 + 1]);
                }
            break;
        }

        #pragma unroll
        for (int rw = 0; rw < 2; rw++) {
            int row = g + 8 * rw;
            bool mb = (s_rst[row * TT + t + 1] != 0);
            #pragma unroll
            for (int hf = 0; hf < 2; hf++) {
                float m0 = mb ? 0.f : hnew[rw][hf * 2];
                float m1 = mb ? 0.f : hnew[rw][hf * 2 + 1];
                uint32_t pk = pkbf(m0, m1);
                uint32_t idx = wbuf * 2112 + row * 132 + 64 * q + 8 * w + hf * 4 + tk;
                s_h32[idx] = pk;
                asm volatile("st.shared::cluster.b32 [%0], %1;"
                             :: "r"(peer_hb + idx * 4), "r"(pk) : "memory");
                hprev[rw][hf * 2]     = m0;
                hprev[rw][hf * 2 + 1] = m1;
            }
        }

        asm volatile("barrier.cluster.arrive.aligned;" ::: "memory");
        #pragma unroll
        for (int rw = 0; rw < 2; rw++)
            #pragma unroll
            for (int hf = 0; hf < 2; hf++) {
                int u = qb + 16 * w + hf * 8 + 2 * tk;
                *(float2*)&g_seq[((size_t)brow[rw] * TT + t) * HID + u] =
                    make_float2(mishf(hnew[rw][hf * 2]), mishf(hnew[rw][hf * 2 + 1]));
            }
        asm volatile("barrier.cluster.wait.aligned;" ::: "memory");
    }
}

// ---- post: out = g_seq @ W_out + b_out (mish precomputed in rec) -----------
__global__ __launch_bounds__(256) void post_kernel(
    const float* __restrict__ W_out, const float* __restrict__ b_out,
    float* __restrict__ out)
{
    __shared__ float s_m2[HID][32];
    __shared__ float s_w[HID * LAT];

    const int tid = threadIdx.x;
    const size_t row0 = (size_t)blockIdx.x * 32;

    for (int i = tid; i < HID * LAT; i += 256) s_w[i] = W_out[i];
    {
        const int row = tid & 31;
        const int kc  = (tid >> 5) * 32;
        const float* src = g_seq + (row0 + row) * HID + kc;
        #pragma unroll
        for (int c = 0; c < 8; c++) {
            float4 v = *(const float4*)(src + 4 * c);
            s_m2[kc + 4 * c + 0][row] = v.x;
            s_m2[kc + 4 * c + 1][row] = v.y;
            s_m2[kc + 4 * c + 2][row] = v.z;
            s_m2[kc + 4 * c + 3][row] = v.w;
        }
    }
    __syncthreads();

    if (tid < 192) {
        const int pg = tid / 24;
        const int l  = tid - pg * 24;
        float2 a0 = make_float2(0.f, 0.f), a1 = make_float2(0.f, 0.f);
        #pragma unroll 4
        for (int k = 0; k < HID; k++) {
            float4 m4 = *(const float4*)&s_m2[k][4 * pg];
            float w = s_w[k * LAT + l];
            float2 w2 = make_float2(w, w);
            fma2(a0, w2, make_float2(m4.x, m4.y));
            fma2(a1, w2, make_float2(m4.z, m4.w));
        }
        const float bl = b_out[l];
        out[(row0 + 4 * pg + 0) * LAT + l] = a0.x + bl;
        out[(row0 + 4 * pg + 1) * LAT + l] = a0.y + bl;
        out[(row0 + 4 * pg + 2) * LAT + l] = a1.x + bl;
        out[(row0 + 4 * pg + 3) * LAT + l] = a1.y + bl;
    }
}

// ---------------------------------------------------------------------------
extern "C" void kernel_launch(void* const* d_in, const int* in_sizes, int n_in,
                              void* d_out, int out_size) {
    const float* obs     = (const float*)d_in[0];
    const int*   is_init = (const int*)  d_in[1];
    const float* hx      = (const float*)d_in[2];
    const float* W_in    = (const float*)d_in[3];
    const float* b_in    = (const float*)d_in[4];
    const float* W_ih    = (const float*)d_in[5];
    const float* b_ih    = (const float*)d_in[6];
    const float* W_hh    = (const float*)d_in[7];
    const float* b_hh    = (const float*)d_in[8];
    const float* W_out   = (const float*)d_in[9];
    const float* b_out   = (const float*)d_in[10];

    float* out     = (float*)d_out;                 // [B,T,LAT]
    float* h_final = out + (size_t)BB * TT * LAT;   // [B,HID]

    cudaFuncSetAttribute(rec_kernel,
                         cudaFuncAttributeMaxDynamicSharedMemorySize, REC_SMEM);

    trm_kernel<<<96, 256>>>(W_hh);
    trmi_kernel<<<48, 256>>>(W_ih);
    preA_kernel<<<(BB * TT) / 32, 256>>>(obs, W_in, b_in);
    preB_kernel<<<(BB * TT) / 32, 256>>>(b_ih);
    rec_kernel<<<128, 256, REC_SMEM>>>(is_init, hx, b_hh, h_final);
    post_kernel<<<(BB * TT) / 32, 256>>>(W_out, b_out, out);
}